// round 2
// baseline (speedup 1.0000x reference)
#include <cuda_runtime.h>
#include <math.h>
#include <stdint.h>

// ---------------- problem constants ----------------
#define Pn 2
#define Bn 2
#define Sn 2048
#define Dn 1024
#define Hn 16
#define DHn 64
#define Rn 16
#define NFQKn 32
#define NFVn 32
#define NRQKn 16
#define TOK (Bn*Sn)            /* 4096 tokens */
#define CDIM (NRQKn*Rn)        /* 256 restore-coefficient dim */

// ---------------- scratch (device globals; no allocs allowed) ----------------
__device__ __align__(16) float g_Fall[(size_t)Dn*1024];      // 1024 x 1024 transposed f_neurons
__device__ __align__(16) float g_AH[(size_t)TOK*Dn];         // all_h (qk cols 0..511, v cols 512..1023)
__device__ __align__(16) float g_C[(size_t)3*TOK*CDIM];      // CQ | CK | CV
__device__ __align__(16) float g_QKV[(size_t)3*TOK*Dn];      // Q | K | V
__device__ __align__(16) float g_AO[(size_t)TOK*Dn];         // attention out (pre-scaled)
__device__ float g_scale[TOK];
__device__ float g_rsum[48];                                 // router weight sums (Q,K,V x 16)

// ---------------- prep: transpose f_neurons, zero rsum ----------------
__global__ void k_prep(const float* __restrict__ fneu) {
    int idx = blockIdx.x * blockDim.x + threadIdx.x;
    if (blockIdx.x == 0 && threadIdx.x < 48) g_rsum[threadIdx.x] = 0.f;
    if (idx < Dn * 1024) {
        int d = idx >> 10, c = idx & 1023;
        int n = c >> 4, r = c & 15;
        // g_Fall[d][n*16+r] = f_neurons[n][d][r]
        g_Fall[idx] = fneu[((size_t)n * Dn + d) * Rn + r];
    }
}

// ---------------- fp32 SGEMM: C[M,N] = A[M,K] @ B[K,N] ----------------
// MODE 0: A=ext(x),      B=g_Fall,  C=g_AH    (M=4096,N=1024,K=1024)
// MODE 1: A=g_C,         B=ext,     C=g_QKV   (M=8192,N=1024,K=256)   [Q,K]
// MODE 2: A=g_C+2*T*C,   B=ext,     C=g_QKV+2*T*D (M=4096,N=1024,K=256) [V]
// MODE 3: A=g_AO,        B=ext,     C=extC    (M=4096,N=1024,K=1024)
#define BM 128
#define BN 128
#define BK 8
template<int MODE>
__global__ __launch_bounds__(256) void k_sgemm(const float* __restrict__ ext,
                                               float* __restrict__ extC,
                                               int M, int N, int K) {
    const float* A;
    const float* B;
    float* C;
    if (MODE == 0) { A = ext;                              B = g_Fall; C = g_AH; }
    if (MODE == 1) { A = g_C;                              B = ext;    C = g_QKV; }
    if (MODE == 2) { A = g_C + (size_t)2 * TOK * CDIM;     B = ext;    C = g_QKV + (size_t)2 * TOK * Dn; }
    if (MODE == 3) { A = g_AO;                             B = ext;    C = extC; }

    __shared__ float As[BK][BM];
    __shared__ float Bs[BK][BN];
    const int tid = threadIdx.x;
    const int bx = blockIdx.x;   // N tile
    const int by = blockIdx.y;   // M tile
    const float* Ab = A + (size_t)by * BM * K;
    const float* Bb = B + (size_t)bx * BN;

    const int arow = tid >> 1;          // 0..127
    const int acol = (tid & 1) << 2;    // 0 or 4
    const int brow = tid >> 5;          // 0..7
    const int bcol = (tid & 31) << 2;   // 0..124
    const int ty = tid >> 4, tx = tid & 15;

    float acc[8][8];
    #pragma unroll
    for (int i = 0; i < 8; i++)
        #pragma unroll
        for (int j = 0; j < 8; j++) acc[i][j] = 0.f;

    for (int k0 = 0; k0 < K; k0 += BK) {
        float4 av = *reinterpret_cast<const float4*>(Ab + (size_t)arow * K + k0 + acol);
        As[acol + 0][arow] = av.x;
        As[acol + 1][arow] = av.y;
        As[acol + 2][arow] = av.z;
        As[acol + 3][arow] = av.w;
        float4 bv = *reinterpret_cast<const float4*>(Bb + (size_t)(k0 + brow) * N + bcol);
        *reinterpret_cast<float4*>(&Bs[brow][bcol]) = bv;
        __syncthreads();
        #pragma unroll
        for (int k = 0; k < BK; k++) {
            float ra[8], rb[8];
            #pragma unroll
            for (int i = 0; i < 8; i++) ra[i] = As[k][ty * 8 + i];
            #pragma unroll
            for (int j = 0; j < 8; j++) rb[j] = Bs[k][tx * 8 + j];
            #pragma unroll
            for (int i = 0; i < 8; i++)
                #pragma unroll
                for (int j = 0; j < 8; j++) acc[i][j] += ra[i] * rb[j];
        }
        __syncthreads();
    }
    float* Cb = C + (size_t)(by * BM) * N + bx * BN;
    #pragma unroll
    for (int i = 0; i < 8; i++) {
        #pragma unroll
        for (int j = 0; j < 8; j += 4) {
            float4 v = make_float4(acc[i][j], acc[i][j + 1], acc[i][j + 2], acc[i][j + 3]);
            *reinterpret_cast<float4*>(Cb + (size_t)(ty * 8 + i) * N + tx * 8 + j) = v;
        }
    }
}

// ---------------- per-token router / coefficient kernel ----------------
// one block (128 threads) per token t = b*S+s
__global__ __launch_bounds__(128) void k_router(
    const float* __restrict__ wQg, const float* __restrict__ wKg, const float* __restrict__ wVg,
    const float* __restrict__ fqk_emb, const float* __restrict__ fv_emb,
    const float* __restrict__ Wp_qk, const float* __restrict__ bp_qk,
    const float* __restrict__ Wp_v, const float* __restrict__ bp_v,
    const float* __restrict__ Wr_qk, const float* __restrict__ Wr_v)
{
    const int t = blockIdx.x;
    const int tid = threadIdx.x;
    __shared__ float AHs[Dn];
    __shared__ float gate[3][32];
    __shared__ float hs[3][16];
    __shared__ float ins[3][128];
    __shared__ float lg[3][16];
    __shared__ float wsm[3][16];

    for (int i = tid; i < Dn; i += 128) AHs[i] = g_AH[(size_t)t * Dn + i];

    float cacc[6] = {0.f, 0.f, 0.f, 0.f, 0.f, 0.f};
    float sumAcc = 0.f;

    for (int p = 0; p < Pn; p++) {
        __syncthreads();
        if (tid < 96) {
            int router = tid >> 5, n = tid & 31;
            const float* src = (router == 0) ? wQg : ((router == 1) ? wKg : wVg);
            gate[router][n] = src[((size_t)p * TOK + t) * 32 + n];
        }
        __syncthreads();
        if (tid < 48) {
            int router = tid >> 4, r = tid & 15;
            int base = (router == 2) ? 512 : 0;
            float a = 0.f;
            #pragma unroll
            for (int n = 0; n < 32; n++) a += gate[router][n] * AHs[base + n * 16 + r];
            hs[router][r] = a;
        }
        __syncthreads();
        for (int v = tid; v < 384; v += 128) {
            int router = v >> 7, i = v & 127;
            float val;
            if (i < 64) {
                const float* Wp = (router == 2) ? Wp_v : Wp_qk;
                const float* bp = (router == 2) ? bp_v : bp_qk;
                float a = bp[i];
                #pragma unroll
                for (int r = 0; r < 16; r++) a += hs[router][r] * Wp[r * 64 + i];
                val = a;
            } else {
                int d = i - 64;
                const float* emb = (router == 2) ? fv_emb : fqk_emb;
                float a = 0.f;
                #pragma unroll
                for (int n = 0; n < 32; n++) a += gate[router][n] * emb[n * 64 + d];
                val = a;
            }
            ins[router][i] = val;
        }
        __syncthreads();
        if (tid < 48) {
            int router = tid >> 4, j = tid & 15;
            const float* Wr = (router == 2) ? Wr_v : Wr_qk;
            float a = 0.f;
            for (int i = 0; i < 128; i++) a += ins[router][i] * Wr[i * 16 + j];
            lg[router][j] = a;
        }
        __syncthreads();
        if (tid < 3) {
            float mx = -1e30f;
            for (int j = 0; j < 16; j++) mx = fmaxf(mx, lg[tid][j]);
            float e[16], s = 0.f;
            for (int j = 0; j < 16; j++) { e[j] = __expf(lg[tid][j] - mx); s += e[j]; }
            float inv = 1.f / s;
            for (int j = 0; j < 16; j++) wsm[tid][j] = e[j] * inv;
        }
        __syncthreads();
        if (tid < 48) sumAcc += wsm[tid >> 4][tid & 15];
        #pragma unroll
        for (int it = 0; it < 6; it++) {
            int v = tid + it * 128;
            int router = v >> 8, idx = v & 255;
            cacc[it] += wsm[router][idx >> 4] * hs[router][idx & 15];
        }
    }
    #pragma unroll
    for (int it = 0; it < 6; it++) {
        int v = tid + it * 128;
        int router = v >> 8, idx = v & 255;
        g_C[((size_t)router * TOK + t) * CDIM + idx] = cacc[it];
    }
    if (tid < 48) atomicAdd(&g_rsum[tid], sumAcc);
}

// ---------------- q-norm -> scale ----------------
__global__ __launch_bounds__(256) void k_qnorm() {
    const int t = blockIdx.x;
    const int tid = threadIdx.x;
    const float* q = g_QKV + (size_t)t * Dn;   // Q block
    float s = 0.f;
    for (int i = tid; i < Dn; i += 256) { float v = q[i]; s += v * v; }
    #pragma unroll
    for (int m = 16; m; m >>= 1) s += __shfl_xor_sync(0xffffffffu, s, m);
    __shared__ float red[8];
    if ((tid & 31) == 0) red[tid >> 5] = s;
    __syncthreads();
    if (tid == 0) {
        float tot = 0.f;
        for (int w = 0; w < 8; w++) tot += red[w];
        float qn = sqrtf(tot);
        g_scale[t] = (qn > 1e-6f) ? 1.0f : qn * 1e-6f;
    }
}

// ---------------- causal flash attention (fp32) ----------------
// grid (S/64, B*H), 256 threads. Q tile 64, K tile 32.
__global__ __launch_bounds__(256) void k_flash() {
    const int qt = blockIdx.x;
    const int bh = blockIdx.y;
    const int b = bh >> 4, h = bh & 15;
    const int tid = threadIdx.x;
    const int ty = tid >> 4, tx = tid & 15;
    const int i0 = ty << 2;
    const int d0 = tx << 2;

    __shared__ float Qs[64][68];
    __shared__ float Ks[32][68];
    __shared__ float Vs[32][68];
    __shared__ float Ps[64][33];

    const float* Qg  = g_QKV + ((size_t)(b * Sn + qt * 64)) * Dn + h * 64;
    const float* Kg0 = g_QKV + (size_t)TOK * Dn + (size_t)b * Sn * Dn + h * 64;
    const float* Vg0 = g_QKV + 2 * (size_t)TOK * Dn + (size_t)b * Sn * Dn + h * 64;

    for (int v = tid; v < 64 * 16; v += 256) {
        int r = v >> 4, c = (v & 15) << 2;
        float4 q4 = *reinterpret_cast<const float4*>(Qg + (size_t)r * Dn + c);
        Qs[r][c] = q4.x; Qs[r][c + 1] = q4.y; Qs[r][c + 2] = q4.z; Qs[r][c + 3] = q4.w;
    }

    float m[4], l[4], o[4][4];
    #pragma unroll
    for (int i = 0; i < 4; i++) {
        m[i] = -1e30f; l[i] = 0.f;
        #pragma unroll
        for (int j = 0; j < 4; j++) o[i][j] = 0.f;
    }

    const int ktmax = 2 * qt + 1;
    for (int kt = 0; kt <= ktmax; kt++) {
        __syncthreads();
        for (int v = tid; v < 32 * 16; v += 256) {
            int r = v >> 4, c = (v & 15) << 2;
            float4 k4 = *reinterpret_cast<const float4*>(Kg0 + (size_t)(kt * 32 + r) * Dn + c);
            Ks[r][c] = k4.x; Ks[r][c + 1] = k4.y; Ks[r][c + 2] = k4.z; Ks[r][c + 3] = k4.w;
            float4 v4 = *reinterpret_cast<const float4*>(Vg0 + (size_t)(kt * 32 + r) * Dn + c);
            Vs[r][c] = v4.x; Vs[r][c + 1] = v4.y; Vs[r][c + 2] = v4.z; Vs[r][c + 3] = v4.w;
        }
        __syncthreads();

        float s[4][2];
        #pragma unroll
        for (int i = 0; i < 4; i++) { s[i][0] = 0.f; s[i][1] = 0.f; }
        #pragma unroll
        for (int d = 0; d < 64; d += 4) {
            float4 k0 = *reinterpret_cast<const float4*>(&Ks[2 * tx][d]);
            float4 k1 = *reinterpret_cast<const float4*>(&Ks[2 * tx + 1][d]);
            #pragma unroll
            for (int i = 0; i < 4; i++) {
                float4 q = *reinterpret_cast<const float4*>(&Qs[i0 + i][d]);
                s[i][0] += q.x * k0.x + q.y * k0.y + q.z * k0.z + q.w * k0.w;
                s[i][1] += q.x * k1.x + q.y * k1.y + q.z * k1.z + q.w * k1.w;
            }
        }

        const bool diag = (kt >= 2 * qt);
        #pragma unroll
        for (int i = 0; i < 4; i++) {
            int ig = qt * 64 + i0 + i;
            float sc0 = s[i][0] * 0.125f;
            float sc1 = s[i][1] * 0.125f;
            if (diag) {
                int jg = kt * 32 + 2 * tx;
                if (jg > ig)     sc0 = -1e30f;
                if (jg + 1 > ig) sc1 = -1e30f;
            }
            float mx = fmaxf(sc0, sc1);
            #pragma unroll
            for (int msk = 8; msk; msk >>= 1) mx = fmaxf(mx, __shfl_xor_sync(0xffffffffu, mx, msk));
            float mnew = fmaxf(m[i], mx);
            float p0 = __expf(sc0 - mnew);
            float p1 = __expf(sc1 - mnew);
            float rs = p0 + p1;
            #pragma unroll
            for (int msk = 8; msk; msk >>= 1) rs += __shfl_xor_sync(0xffffffffu, rs, msk);
            float corr = __expf(m[i] - mnew);
            m[i] = mnew;
            l[i] = l[i] * corr + rs;
            #pragma unroll
            for (int jj = 0; jj < 4; jj++) o[i][jj] *= corr;
            Ps[i0 + i][2 * tx] = p0;
            Ps[i0 + i][2 * tx + 1] = p1;
        }
        __syncwarp();
        #pragma unroll
        for (int j = 0; j < 32; j++) {
            float4 v4 = *reinterpret_cast<const float4*>(&Vs[j][d0]);
            #pragma unroll
            for (int i = 0; i < 4; i++) {
                float p = Ps[i0 + i][j];
                o[i][0] += p * v4.x; o[i][1] += p * v4.y;
                o[i][2] += p * v4.z; o[i][3] += p * v4.w;
            }
        }
    }

    #pragma unroll
    for (int i = 0; i < 4; i++) {
        int sg = qt * 64 + i0 + i;
        float f = g_scale[b * Sn + sg] / l[i];
        float4 w4 = make_float4(o[i][0] * f, o[i][1] * f, o[i][2] * f, o[i][3] * f);
        *reinterpret_cast<float4*>(g_AO + ((size_t)(b * Sn + sg)) * Dn + h * 64 + d0) = w4;
    }
}

// ---------------- aux loss ----------------
__global__ void k_aux(float* __restrict__ out) {
    float aux = 0.f;
    for (int router = 0; router < 3; router++) {
        float s = 0.f;
        for (int j = 0; j < 16; j++) {
            float mp = g_rsum[router * 16 + j] / (float)(Pn * TOK);
            s += mp * mp;
        }
        aux += 16.f * s;
    }
    out[(size_t)TOK * Dn] = aux;
}

// ---------------- launch ----------------
extern "C" void kernel_launch(void* const* d_in, const int* in_sizes, int n_in,
                              void* d_out, int out_size) {
    const float* x       = (const float*)d_in[0];
    const float* wQ      = (const float*)d_in[1];
    const float* wK      = (const float*)d_in[2];
    const float* wV      = (const float*)d_in[3];
    const float* fneu    = (const float*)d_in[4];
    const float* rneu    = (const float*)d_in[5];
    const float* fqk_emb = (const float*)d_in[6];
    const float* fv_emb  = (const float*)d_in[7];
    const float* Wp_qk   = (const float*)d_in[8];
    const float* bp_qk   = (const float*)d_in[9];
    const float* Wp_v    = (const float*)d_in[10];
    const float* bp_v    = (const float*)d_in[11];
    const float* Wr_qk   = (const float*)d_in[12];
    const float* Wr_v    = (const float*)d_in[13];
    const float* W_O     = (const float*)d_in[14];
    float* out = (float*)d_out;

    // 1. transpose f_neurons (+ zero router sums)
    k_prep<<<4096, 256>>>(fneu);
    // 2. all_h = X @ Fall   (4096 x 1024 x 1024)
    k_sgemm<0><<<dim3(Dn / BN, TOK / BM), 256>>>(x, nullptr, TOK, Dn, Dn);
    // 3. router + restore coefficients
    k_router<<<TOK, 128>>>(wQ, wK, wV, fqk_emb, fv_emb, Wp_qk, bp_qk, Wp_v, bp_v, Wr_qk, Wr_v);
    // 4. Q,K = [CQ;CK] @ r_qk ; V = CV @ r_v
    k_sgemm<1><<<dim3(Dn / BN, 2 * TOK / BM), 256>>>(rneu, nullptr, 2 * TOK, Dn, CDIM);
    k_sgemm<2><<<dim3(Dn / BN, TOK / BM), 256>>>(rneu + (size_t)NRQKn * Rn * Dn, nullptr, TOK, Dn, CDIM);
    // 5. scale from |Q|
    k_qnorm<<<TOK, 256>>>();
    // 6. flash attention (causal), writes pre-scaled attn_out
    k_flash<<<dim3(Sn / 64, Bn * Hn), 256>>>();
    // 7. out = AO @ W_O
    k_sgemm<3><<<dim3(Dn / BN, TOK / BM), 256>>>(W_O, out, TOK, Dn, Dn);
    // 8. aux loss scalar
    if (out_size > TOK * Dn) k_aux<<<1, 1>>>(out);
}

// round 4
// speedup vs baseline: 1.2885x; 1.2885x over previous
#include <cuda_runtime.h>
#include <math.h>
#include <stdint.h>

// ---------------- problem constants ----------------
#define Pn 2
#define Bn 2
#define Sn 2048
#define Dn 1024
#define Hn 16
#define DHn 64
#define Rn 16
#define NRQKn 16
#define TOK (Bn*Sn)            /* 4096 tokens */
#define CDIM (NRQKn*Rn)        /* 256 restore-coefficient dim */

// ---------------- scratch (device globals) ----------------
__device__ __align__(16) float g_Fall[(size_t)Dn*1024];
__device__ __align__(16) float g_AH[(size_t)TOK*Dn];
__device__ __align__(16) float g_C[(size_t)3*TOK*CDIM];
__device__ __align__(16) float g_QKV[(size_t)3*TOK*Dn];
__device__ __align__(16) float g_AO[(size_t)TOK*Dn];
__device__ float g_scale[TOK];
__device__ float g_rsum[48];

// ---------------- helpers ----------------
__device__ __forceinline__ uint32_t f2tf(float x) {
    uint32_t r;
    asm("cvt.rna.tf32.f32 %0, %1;" : "=r"(r) : "f"(x));
    return r;
}
// split x into tf32 hi + tf32 lo (3xTF32 trick)
__device__ __forceinline__ uint2 tfsplit(float x) {
    uint32_t hi = f2tf(x);
    uint32_t lo = f2tf(x - __uint_as_float(hi));
    return make_uint2(hi, lo);
}
__device__ __forceinline__ void mma_tf32(float* d, const uint32_t* a, uint32_t b0, uint32_t b1) {
    asm volatile("mma.sync.aligned.m16n8k8.row.col.f32.tf32.tf32.f32 "
                 "{%0,%1,%2,%3},{%4,%5,%6,%7},{%8,%9},{%0,%1,%2,%3};"
                 : "+f"(d[0]), "+f"(d[1]), "+f"(d[2]), "+f"(d[3])
                 : "r"(a[0]), "r"(a[1]), "r"(a[2]), "r"(a[3]), "r"(b0), "r"(b1));
}

// ---------------- prep: transpose f_neurons, zero rsum ----------------
__global__ void k_prep(const float* __restrict__ fneu) {
    int idx = blockIdx.x * blockDim.x + threadIdx.x;
    if (blockIdx.x == 0 && threadIdx.x < 48) g_rsum[threadIdx.x] = 0.f;
    if (idx < Dn * 1024) {
        int d = idx >> 10, c = idx & 1023;
        int n = c >> 4, r = c & 15;
        g_Fall[idx] = fneu[((size_t)n * Dn + d) * Rn + r];
    }
}

// ---------------- 3xtf32 tensor-core GEMM: C[M,N] = A[M,K] @ B[K,N] ----------------
// block tile 128x128x16, 8 warps (4x2), warp tile 32x64. M%128==0, N%128==0, K%16==0.
#define GAS 20    /* As row stride in uint2 (pairs); 20 mod 16 == 4 -> conflict-free */
#define GBS 132   /* Bs row stride in uint2; 132 mod 16 == 4 */
template<int MODE>
__global__ __launch_bounds__(256) void k_mma(const float* __restrict__ ext,
                                             float* __restrict__ extC,
                                             int M, int N, int K) {
    const float* A; const float* B; float* C;
    if (MODE == 0) { A = ext;                          B = g_Fall; C = g_AH; }
    if (MODE == 1) { A = g_C;                          B = ext;    C = g_QKV; }
    if (MODE == 2) { A = g_C + (size_t)2 * TOK * CDIM; B = ext;    C = g_QKV + (size_t)2 * TOK * Dn; }
    if (MODE == 3) { A = g_AO;                         B = ext;    C = extC; }

    __shared__ uint2 As[128][GAS];   // [row][k] (hi,lo)
    __shared__ uint2 Bs[16][GBS];    // [k][col] (hi,lo)

    const int tid  = threadIdx.x;
    const int lane = tid & 31;
    const int warp = tid >> 5;
    const int wr = warp >> 1;          // 0..3
    const int wc = warp & 1;           // 0..1
    const int g = lane >> 2;           // 0..7
    const int t = lane & 3;            // 0..3
    const int bx = blockIdx.x, by = blockIdx.y;

    float acc[2][8][4];
    #pragma unroll
    for (int mi = 0; mi < 2; mi++)
        #pragma unroll
        for (int ni = 0; ni < 8; ni++)
            #pragma unroll
            for (int j = 0; j < 4; j++) acc[mi][ni][j] = 0.f;

    const int ar = tid >> 2;               // 0..63
    const int ac = (tid & 3) << 2;         // 0,4,8,12
    const int br = tid >> 4;               // 0..15
    const int bc = (tid & 15) << 2;        // 0..60

    for (int k0 = 0; k0 < K; k0 += 16) {
        #pragma unroll
        for (int i = 0; i < 2; i++) {
            int r = ar + i * 64;
            float4 v = *reinterpret_cast<const float4*>(A + (size_t)(by * 128 + r) * K + k0 + ac);
            As[r][ac + 0] = tfsplit(v.x); As[r][ac + 1] = tfsplit(v.y);
            As[r][ac + 2] = tfsplit(v.z); As[r][ac + 3] = tfsplit(v.w);
        }
        #pragma unroll
        for (int i = 0; i < 2; i++) {
            int c = bc + i * 64;
            float4 v = *reinterpret_cast<const float4*>(B + (size_t)(k0 + br) * N + bx * 128 + c);
            Bs[br][c + 0] = tfsplit(v.x); Bs[br][c + 1] = tfsplit(v.y);
            Bs[br][c + 2] = tfsplit(v.z); Bs[br][c + 3] = tfsplit(v.w);
        }
        __syncthreads();
        #pragma unroll
        for (int kk = 0; kk < 16; kk += 8) {
            uint32_t ah[2][4], al[2][4];
            #pragma unroll
            for (int mi = 0; mi < 2; mi++) {
                int r0 = wr * 32 + mi * 16 + g;
                uint2 a0 = As[r0][kk + t];
                uint2 a1 = As[r0 + 8][kk + t];
                uint2 a2 = As[r0][kk + 4 + t];
                uint2 a3 = As[r0 + 8][kk + 4 + t];
                ah[mi][0] = a0.x; ah[mi][1] = a1.x; ah[mi][2] = a2.x; ah[mi][3] = a3.x;
                al[mi][0] = a0.y; al[mi][1] = a1.y; al[mi][2] = a2.y; al[mi][3] = a3.y;
            }
            #pragma unroll
            for (int ni = 0; ni < 8; ni++) {
                int c = wc * 64 + ni * 8 + g;
                uint2 b0 = Bs[kk + t][c];
                uint2 b1 = Bs[kk + 4 + t][c];
                #pragma unroll
                for (int mi = 0; mi < 2; mi++) {
                    mma_tf32(acc[mi][ni], ah[mi], b0.x, b1.x);
                    mma_tf32(acc[mi][ni], al[mi], b0.x, b1.x);
                    mma_tf32(acc[mi][ni], ah[mi], b0.y, b1.y);
                }
            }
        }
        __syncthreads();
    }
    #pragma unroll
    for (int mi = 0; mi < 2; mi++) {
        int r0 = by * 128 + wr * 32 + mi * 16 + g;
        #pragma unroll
        for (int ni = 0; ni < 8; ni++) {
            int c = bx * 128 + wc * 64 + ni * 8 + 2 * t;
            *reinterpret_cast<float2*>(C + (size_t)r0 * N + c) =
                make_float2(acc[mi][ni][0], acc[mi][ni][1]);
            *reinterpret_cast<float2*>(C + (size_t)(r0 + 8) * N + c) =
                make_float2(acc[mi][ni][2], acc[mi][ni][3]);
        }
    }
}

// ---------------- per-token router / coefficient kernel ----------------
__global__ __launch_bounds__(128) void k_router(
    const float* __restrict__ wQg, const float* __restrict__ wKg, const float* __restrict__ wVg,
    const float* __restrict__ fqk_emb, const float* __restrict__ fv_emb,
    const float* __restrict__ Wp_qk, const float* __restrict__ bp_qk,
    const float* __restrict__ Wp_v, const float* __restrict__ bp_v,
    const float* __restrict__ Wr_qk, const float* __restrict__ Wr_v)
{
    const int t = blockIdx.x;
    const int tid = threadIdx.x;
    __shared__ float AHs[Dn];
    __shared__ float gate[3][32];
    __shared__ float hs[3][16];
    __shared__ float ins[3][128];
    __shared__ float lg[3][16];
    __shared__ float wsm[3][16];

    for (int i = tid; i < Dn; i += 128) AHs[i] = g_AH[(size_t)t * Dn + i];

    float cacc[6] = {0.f, 0.f, 0.f, 0.f, 0.f, 0.f};
    float sumAcc = 0.f;

    for (int p = 0; p < Pn; p++) {
        __syncthreads();
        if (tid < 96) {
            int router = tid >> 5, n = tid & 31;
            const float* src = (router == 0) ? wQg : ((router == 1) ? wKg : wVg);
            gate[router][n] = src[((size_t)p * TOK + t) * 32 + n];
        }
        __syncthreads();
        if (tid < 48) {
            int router = tid >> 4, r = tid & 15;
            int base = (router == 2) ? 512 : 0;
            float a = 0.f;
            #pragma unroll
            for (int n = 0; n < 32; n++) a += gate[router][n] * AHs[base + n * 16 + r];
            hs[router][r] = a;
        }
        __syncthreads();
        for (int v = tid; v < 384; v += 128) {
            int router = v >> 7, i = v & 127;
            float val;
            if (i < 64) {
                const float* Wp = (router == 2) ? Wp_v : Wp_qk;
                const float* bp = (router == 2) ? bp_v : bp_qk;
                float a = bp[i];
                #pragma unroll
                for (int r = 0; r < 16; r++) a += hs[router][r] * Wp[r * 64 + i];
                val = a;
            } else {
                int d = i - 64;
                const float* emb = (router == 2) ? fv_emb : fqk_emb;
                float a = 0.f;
                #pragma unroll
                for (int n = 0; n < 32; n++) a += gate[router][n] * emb[n * 64 + d];
                val = a;
            }
            ins[router][i] = val;
        }
        __syncthreads();
        if (tid < 48) {
            int router = tid >> 4, j = tid & 15;
            const float* Wr = (router == 2) ? Wr_v : Wr_qk;
            float a = 0.f;
            for (int i = 0; i < 128; i++) a += ins[router][i] * Wr[i * 16 + j];
            lg[router][j] = a;
        }
        __syncthreads();
        if (tid < 3) {
            float mx = -1e30f;
            for (int j = 0; j < 16; j++) mx = fmaxf(mx, lg[tid][j]);
            float e[16], s = 0.f;
            for (int j = 0; j < 16; j++) { e[j] = __expf(lg[tid][j] - mx); s += e[j]; }
            float inv = 1.f / s;
            for (int j = 0; j < 16; j++) wsm[tid][j] = e[j] * inv;
        }
        __syncthreads();
        if (tid < 48) sumAcc += wsm[tid >> 4][tid & 15];
        #pragma unroll
        for (int it = 0; it < 6; it++) {
            int v = tid + it * 128;
            int router = v >> 8, idx = v & 255;
            cacc[it] += wsm[router][idx >> 4] * hs[router][idx & 15];
        }
    }
    #pragma unroll
    for (int it = 0; it < 6; it++) {
        int v = tid + it * 128;
        int router = v >> 8, idx = v & 255;
        g_C[((size_t)router * TOK + t) * CDIM + idx] = cacc[it];
    }
    if (tid < 48) atomicAdd(&g_rsum[tid], sumAcc);
}

// ---------------- q-norm -> scale ----------------
__global__ __launch_bounds__(256) void k_qnorm() {
    const int t = blockIdx.x;
    const int tid = threadIdx.x;
    const float* q = g_QKV + (size_t)t * Dn;
    float s = 0.f;
    for (int i = tid; i < Dn; i += 256) { float v = q[i]; s += v * v; }
    #pragma unroll
    for (int m = 16; m; m >>= 1) s += __shfl_xor_sync(0xffffffffu, s, m);
    __shared__ float red[8];
    if ((tid & 31) == 0) red[tid >> 5] = s;
    __syncthreads();
    if (tid == 0) {
        float tot = 0.f;
        for (int w = 0; w < 8; w++) tot += red[w];
        float qn = sqrtf(tot);
        g_scale[t] = (qn > 1e-6f) ? 1.0f : qn * 1e-6f;
    }
}

// ---------------- 3xtf32 tensor-core causal flash attention ----------------
// grid (S/128, B*H), 256 threads (8 warps), warp = 16 q rows, KV tile = 32.
#define FKS 68    /* K/V row stride in uint2 pairs; 68 mod 16 == 4 */
__global__ __launch_bounds__(256) void k_flashmma() {
    const int qt = blockIdx.x;
    const int bh = blockIdx.y;
    const int b = bh >> 4, h = bh & 15;
    const int tid = threadIdx.x;
    const int lane = tid & 31;
    const int warp = tid >> 5;
    const int g = lane >> 2, t = lane & 3;
    const int q0 = qt * 128 + warp * 16;     // warp's first q row

    __shared__ uint2 Ks[32][FKS];   // [key][d] (hi,lo)
    __shared__ uint2 Vs[32][FKS];   // [key][d] (hi,lo)

    const float* Qg = g_QKV + (size_t)b * Sn * Dn + (size_t)h * 64;
    const float* Kg = g_QKV + (size_t)TOK * Dn + (size_t)b * Sn * Dn + (size_t)h * 64;
    const float* Vg = g_QKV + 2 * (size_t)TOK * Dn + (size_t)b * Sn * Dn + (size_t)h * 64;

    // Q fragments (hi/lo), pre-scaled by 0.125 (exact power of 2)
    uint32_t qh[8][4], ql[8][4];
    {
        const int r0 = q0 + g, r1 = r0 + 8;
        #pragma unroll
        for (int ka = 0; ka < 8; ka++) {
            int c = ka * 8 + t;
            uint2 s0 = tfsplit(0.125f * Qg[(size_t)r0 * Dn + c]);
            uint2 s1 = tfsplit(0.125f * Qg[(size_t)r1 * Dn + c]);
            uint2 s2 = tfsplit(0.125f * Qg[(size_t)r0 * Dn + c + 4]);
            uint2 s3 = tfsplit(0.125f * Qg[(size_t)r1 * Dn + c + 4]);
            qh[ka][0] = s0.x; qh[ka][1] = s1.x; qh[ka][2] = s2.x; qh[ka][3] = s3.x;
            ql[ka][0] = s0.y; ql[ka][1] = s1.y; ql[ka][2] = s2.y; ql[ka][3] = s3.y;
        }
    }

    float o[8][4];
    #pragma unroll
    for (int ni = 0; ni < 8; ni++)
        #pragma unroll
        for (int j = 0; j < 4; j++) o[ni][j] = 0.f;
    float m0 = -1e30f, m1 = -1e30f, l0 = 0.f, l1 = 0.f;

    const int srcA = (lane & ~3) | (t >> 1);
    const int srcB = srcA + 2;
    const bool odd = t & 1;

    const int nkt = 4 * qt + 4;
    for (int kt = 0; kt < nkt; kt++) {
        __syncthreads();
        #pragma unroll
        for (int i = 0; i < 2; i++) {
            int id = tid + i * 256;
            int r = id >> 4, c = (id & 15) << 2;
            float4 k4 = *reinterpret_cast<const float4*>(Kg + (size_t)(kt * 32 + r) * Dn + c);
            Ks[r][c + 0] = tfsplit(k4.x); Ks[r][c + 1] = tfsplit(k4.y);
            Ks[r][c + 2] = tfsplit(k4.z); Ks[r][c + 3] = tfsplit(k4.w);
            float4 v4 = *reinterpret_cast<const float4*>(Vg + (size_t)(kt * 32 + r) * Dn + c);
            Vs[r][c + 0] = tfsplit(v4.x); Vs[r][c + 1] = tfsplit(v4.y);
            Vs[r][c + 2] = tfsplit(v4.z); Vs[r][c + 3] = tfsplit(v4.w);
        }
        __syncthreads();

        if (kt * 32 > q0 + 15) continue;   // fully masked for this warp

        // S = Q @ K^T  (16 x 32), 3xtf32
        float s[4][4];
        #pragma unroll
        for (int ni = 0; ni < 4; ni++)
            #pragma unroll
            for (int j = 0; j < 4; j++) s[ni][j] = 0.f;
        #pragma unroll
        for (int ka = 0; ka < 8; ka++) {
            #pragma unroll
            for (int ni = 0; ni < 4; ni++) {
                uint2 b0 = Ks[ni * 8 + g][ka * 8 + t];
                uint2 b1 = Ks[ni * 8 + g][ka * 8 + t + 4];
                mma_tf32(s[ni], qh[ka], b0.x, b1.x);
                mma_tf32(s[ni], ql[ka], b0.x, b1.x);
                mma_tf32(s[ni], qh[ka], b0.y, b1.y);
            }
        }

        // causal mask (diagonal tiles only)
        if (kt * 32 + 31 > q0) {
            const int r0 = q0 + g, r1 = r0 + 8, cb = kt * 32;
            #pragma unroll
            for (int ni = 0; ni < 4; ni++) {
                int c0 = cb + ni * 8 + 2 * t;
                if (c0 > r0)     s[ni][0] = -1e30f;
                if (c0 + 1 > r0) s[ni][1] = -1e30f;
                if (c0 > r1)     s[ni][2] = -1e30f;
                if (c0 + 1 > r1) s[ni][3] = -1e30f;
            }
        }

        // online softmax: max pass
        float mx0 = -1e30f, mx1 = -1e30f;
        #pragma unroll
        for (int ni = 0; ni < 4; ni++) {
            mx0 = fmaxf(mx0, fmaxf(s[ni][0], s[ni][1]));
            mx1 = fmaxf(mx1, fmaxf(s[ni][2], s[ni][3]));
        }
        mx0 = fmaxf(mx0, __shfl_xor_sync(0xffffffffu, mx0, 1));
        mx0 = fmaxf(mx0, __shfl_xor_sync(0xffffffffu, mx0, 2));
        mx1 = fmaxf(mx1, __shfl_xor_sync(0xffffffffu, mx1, 1));
        mx1 = fmaxf(mx1, __shfl_xor_sync(0xffffffffu, mx1, 2));
        float mn0 = fmaxf(m0, mx0), mn1 = fmaxf(m1, mx1);
        float cr0 = __expf(m0 - mn0), cr1 = __expf(m1 - mn1);
        m0 = mn0; m1 = mn1;
        #pragma unroll
        for (int ni = 0; ni < 8; ni++) {
            o[ni][0] *= cr0; o[ni][1] *= cr0;
            o[ni][2] *= cr1; o[ni][3] *= cr1;
        }

        // fused exp -> fragment-transpose -> PV mma, per S fragment
        float rs0 = 0.f, rs1 = 0.f;
        #pragma unroll
        for (int f = 0; f < 4; f++) {
            float p0 = __expf(s[f][0] - m0);
            float p1 = __expf(s[f][1] - m0);
            float p2 = __expf(s[f][2] - m1);
            float p3 = __expf(s[f][3] - m1);
            rs0 += p0 + p1; rs1 += p2 + p3;
            uint2 t0 = tfsplit(p0), t1 = tfsplit(p1), t2 = tfsplit(p2), t3 = tfsplit(p3);
            uint32_t ph[4], pl[4];
            {
                uint32_t x0 = __shfl_sync(0xffffffffu, t0.x, srcA);
                uint32_t x1 = __shfl_sync(0xffffffffu, t1.x, srcA);
                ph[0] = odd ? x1 : x0;
                uint32_t y0 = __shfl_sync(0xffffffffu, t2.x, srcA);
                uint32_t y1 = __shfl_sync(0xffffffffu, t3.x, srcA);
                ph[1] = odd ? y1 : y0;
                uint32_t z0 = __shfl_sync(0xffffffffu, t0.x, srcB);
                uint32_t z1 = __shfl_sync(0xffffffffu, t1.x, srcB);
                ph[2] = odd ? z1 : z0;
                uint32_t w0 = __shfl_sync(0xffffffffu, t2.x, srcB);
                uint32_t w1 = __shfl_sync(0xffffffffu, t3.x, srcB);
                ph[3] = odd ? w1 : w0;
                uint32_t u0 = __shfl_sync(0xffffffffu, t0.y, srcA);
                uint32_t u1 = __shfl_sync(0xffffffffu, t1.y, srcA);
                pl[0] = odd ? u1 : u0;
                uint32_t v0 = __shfl_sync(0xffffffffu, t2.y, srcA);
                uint32_t v1 = __shfl_sync(0xffffffffu, t3.y, srcA);
                pl[1] = odd ? v1 : v0;
                uint32_t q0s = __shfl_sync(0xffffffffu, t0.y, srcB);
                uint32_t q1s = __shfl_sync(0xffffffffu, t1.y, srcB);
                pl[2] = odd ? q1s : q0s;
                uint32_t r0s = __shfl_sync(0xffffffffu, t2.y, srcB);
                uint32_t r1s = __shfl_sync(0xffffffffu, t3.y, srcB);
                pl[3] = odd ? r1s : r0s;
            }
            #pragma unroll
            for (int ni = 0; ni < 8; ni++) {
                uint2 v0 = Vs[f * 8 + t][ni * 8 + g];
                uint2 v1 = Vs[f * 8 + 4 + t][ni * 8 + g];
                mma_tf32(o[ni], ph, v0.x, v1.x);
                mma_tf32(o[ni], pl, v0.x, v1.x);
                mma_tf32(o[ni], ph, v0.y, v1.y);
            }
        }
        rs0 += __shfl_xor_sync(0xffffffffu, rs0, 1);
        rs0 += __shfl_xor_sync(0xffffffffu, rs0, 2);
        rs1 += __shfl_xor_sync(0xffffffffu, rs1, 1);
        rs1 += __shfl_xor_sync(0xffffffffu, rs1, 2);
        l0 = l0 * cr0 + rs0;
        l1 = l1 * cr1 + rs1;
    }

    // epilogue: normalize, apply q-norm scale, write
    const int r0 = q0 + g, r1 = r0 + 8;
    const int tb = b * Sn;
    float f0 = g_scale[tb + r0] / l0;
    float f1 = g_scale[tb + r1] / l1;
    #pragma unroll
    for (int ni = 0; ni < 8; ni++) {
        int c = h * 64 + ni * 8 + 2 * t;
        *reinterpret_cast<float2*>(g_AO + (size_t)(tb + r0) * Dn + c) =
            make_float2(o[ni][0] * f0, o[ni][1] * f0);
        *reinterpret_cast<float2*>(g_AO + (size_t)(tb + r1) * Dn + c) =
            make_float2(o[ni][2] * f1, o[ni][3] * f1);
    }
}

// ---------------- aux loss ----------------
__global__ void k_aux(float* __restrict__ out) {
    float aux = 0.f;
    for (int router = 0; router < 3; router++) {
        float s = 0.f;
        for (int j = 0; j < 16; j++) {
            float mp = g_rsum[router * 16 + j] / (float)(Pn * TOK);
            s += mp * mp;
        }
        aux += 16.f * s;
    }
    out[(size_t)TOK * Dn] = aux;
}

// ---------------- launch ----------------
extern "C" void kernel_launch(void* const* d_in, const int* in_sizes, int n_in,
                              void* d_out, int out_size) {
    const float* x       = (const float*)d_in[0];
    const float* wQ      = (const float*)d_in[1];
    const float* wK      = (const float*)d_in[2];
    const float* wV      = (const float*)d_in[3];
    const float* fneu    = (const float*)d_in[4];
    const float* rneu    = (const float*)d_in[5];
    const float* fqk_emb = (const float*)d_in[6];
    const float* fv_emb  = (const float*)d_in[7];
    const float* Wp_qk   = (const float*)d_in[8];
    const float* bp_qk   = (const float*)d_in[9];
    const float* Wp_v    = (const float*)d_in[10];
    const float* bp_v    = (const float*)d_in[11];
    const float* Wr_qk   = (const float*)d_in[12];
    const float* Wr_v    = (const float*)d_in[13];
    const float* W_O     = (const float*)d_in[14];
    float* out = (float*)d_out;

    k_prep<<<4096, 256>>>(fneu);
    // all_h = X @ Fall   (4096 x 1024 x 1024)
    k_mma<0><<<dim3(Dn / 128, TOK / 128), 256>>>(x, nullptr, TOK, Dn, Dn);
    k_router<<<TOK, 128>>>(wQ, wK, wV, fqk_emb, fv_emb, Wp_qk, bp_qk, Wp_v, bp_v, Wr_qk, Wr_v);
    // Q,K = [CQ;CK] @ r_qk ; V = CV @ r_v
    k_mma<1><<<dim3(Dn / 128, 2 * TOK / 128), 256>>>(rneu, nullptr, 2 * TOK, Dn, CDIM);
    k_mma<2><<<dim3(Dn / 128, TOK / 128), 256>>>(rneu + (size_t)NRQKn * Rn * Dn, nullptr, TOK, Dn, CDIM);
    k_qnorm<<<TOK, 256>>>();
    k_flashmma<<<dim3(Sn / 128, Bn * Hn), 256>>>();
    // out = AO @ W_O
    k_mma<3><<<dim3(Dn / 128, TOK / 128), 256>>>(W_O, out, TOK, Dn, Dn);
    if (out_size > TOK * Dn) k_aux<<<1, 1>>>(out);
}

// round 6
// speedup vs baseline: 1.3709x; 1.0639x over previous
#include <cuda_runtime.h>
#include <math.h>
#include <stdint.h>

// ---------------- problem constants ----------------
#define Pn 2
#define Bn 2
#define Sn 2048
#define Dn 1024
#define Hn 16
#define DHn 64
#define Rn 16
#define NRQKn 16
#define TOK (Bn*Sn)            /* 4096 tokens */
#define CDIM (NRQKn*Rn)        /* 256 restore-coefficient dim */

// ---------------- scratch (device globals) ----------------
__device__ __align__(16) uint2 g_Falls[(size_t)Dn*1024];     // split transposed f_neurons
__device__ __align__(16) uint2 g_Xs[(size_t)TOK*Dn];         // split x
__device__ __align__(16) uint2 g_Rs[(size_t)512*1024];       // split r_neurons (qk then v)
__device__ __align__(16) uint2 g_WOs[(size_t)Dn*Dn];         // split W_O
__device__ __align__(16) uint2 g_Cs[(size_t)3*TOK*CDIM];     // split CQ|CK|CV
__device__ __align__(16) uint2 g_QKVs[(size_t)3*TOK*Dn];     // split Q|K|V
__device__ __align__(16) uint2 g_AOs[(size_t)TOK*Dn];        // split attention out
__device__ __align__(16) float g_AH[(size_t)TOK*Dn];         // all_h (float, for router)
__device__ __align__(16) float g_Qf[(size_t)TOK*Dn];         // Q float (for qnorm)
__device__ float g_scale[TOK];
__device__ float g_rsum[48];

// ---------------- helpers ----------------
__device__ __forceinline__ uint32_t f2tf(float x) {
    uint32_t r;
    asm("cvt.rna.tf32.f32 %0, %1;" : "=r"(r) : "f"(x));
    return r;
}
__device__ __forceinline__ uint2 tfsplit(float x) {
    uint32_t hi = f2tf(x);
    uint32_t lo = f2tf(x - __uint_as_float(hi));
    return make_uint2(hi, lo);
}
__device__ __forceinline__ void mma_tf32(float* d, const uint32_t* a, uint32_t b0, uint32_t b1) {
    asm volatile("mma.sync.aligned.m16n8k8.row.col.f32.tf32.tf32.f32 "
                 "{%0,%1,%2,%3},{%4,%5,%6,%7},{%8,%9},{%0,%1,%2,%3};"
                 : "+f"(d[0]), "+f"(d[1]), "+f"(d[2]), "+f"(d[3])
                 : "r"(a[0]), "r"(a[1]), "r"(a[2]), "r"(a[3]), "r"(b0), "r"(b1));
}
__device__ __forceinline__ void cpa16(void* smem, const void* gmem) {
    uint32_t s = (uint32_t)__cvta_generic_to_shared(smem);
    asm volatile("cp.async.cg.shared.global [%0], [%1], 16;" :: "r"(s), "l"(gmem) : "memory");
}
__device__ __forceinline__ void cpcommit() { asm volatile("cp.async.commit_group;" ::: "memory"); }
__device__ __forceinline__ void cpwait0()  { asm volatile("cp.async.wait_group 0;" ::: "memory"); }

// ---------------- prep: transpose+split f_neurons, zero rsum ----------------
__global__ void k_prep(const float* __restrict__ fneu) {
    int idx = blockIdx.x * blockDim.x + threadIdx.x;
    if (blockIdx.x == 0 && threadIdx.x < 48) g_rsum[threadIdx.x] = 0.f;
    if (idx < Dn * 1024) {
        int d = idx >> 10, c = idx & 1023;
        int n = c >> 4, r = c & 15;
        g_Falls[idx] = tfsplit(fneu[((size_t)n * Dn + d) * Rn + r]);
    }
}

// ---------------- generic split kernels ----------------
template<int W>
__global__ void k_split(const float* __restrict__ src, int n) {
    int idx = blockIdx.x * blockDim.x + threadIdx.x;
    if (idx < n) {
        uint2 v = tfsplit(src[idx]);
        if (W == 0) g_Xs[idx]  = v;
        if (W == 1) g_Rs[idx]  = v;
        if (W == 2) g_WOs[idx] = v;
    }
}

// ---------------- 3xtf32 double-buffered GEMM: C[M,N] = A @ B, N=1024 ----------------
// block tile 128x128x8, 8 warps (4x2). Operands pre-split in global (uint2).
#define GAS 12    /* As row stride in pairs */
#define GBS 132   /* Bs row stride in pairs */
template<int MODE>
__global__ __launch_bounds__(256) void k_mma(float* __restrict__ extC) {
    constexpr int K = (MODE == 1 || MODE == 2) ? CDIM : 1024;
    constexpr int N = 1024;

    const uint2* A; const uint2* B;
    if (MODE == 0) { A = g_Xs;                          B = g_Falls; }
    if (MODE == 1) { A = g_Cs;                          B = g_Rs; }
    if (MODE == 2) { A = g_Cs + (size_t)2 * TOK * CDIM; B = g_Rs + (size_t)256 * 1024; }
    if (MODE == 3) { A = g_AOs;                         B = g_WOs; }

    __shared__ uint2 As[2][128][GAS];
    __shared__ uint2 Bs[2][8][GBS];

    const int tid  = threadIdx.x;
    const int lane = tid & 31;
    const int warp = tid >> 5;
    const int wr = warp >> 1;
    const int wc = warp & 1;
    const int g = lane >> 2;
    const int t = lane & 3;
    const int bx = blockIdx.x, by = blockIdx.y;

    float acc[2][8][4];
    #pragma unroll
    for (int mi = 0; mi < 2; mi++)
        #pragma unroll
        for (int ni = 0; ni < 8; ni++)
            #pragma unroll
            for (int j = 0; j < 4; j++) acc[mi][ni][j] = 0.f;

    const uint2* Ab = A + (size_t)by * 128 * K;
    const uint2* Bb = B + (size_t)bx * 128;

    // stage loader: A tile 128x8 pairs, B tile 8x128 pairs
    auto loadStage = [&](int st, int k0) {
        #pragma unroll
        for (int i = 0; i < 2; i++) {
            int chunk = tid + i * 256;              // 0..511
            int r = chunk >> 2, c4 = (chunk & 3) * 2;
            cpa16(&As[st][r][c4], Ab + (size_t)r * K + k0 + c4);
        }
        #pragma unroll
        for (int i = 0; i < 2; i++) {
            int chunk = tid + i * 256;              // 0..511
            int kr = chunk >> 6, c4 = (chunk & 63) * 2;
            cpa16(&Bs[st][kr][c4], Bb + (size_t)(k0 + kr) * N + c4);
        }
    };

    loadStage(0, 0);
    cpcommit();

    constexpr int NIT = K / 8;
    for (int it = 0; it < NIT; it++) {
        cpwait0();
        __syncthreads();
        if (it + 1 < NIT) { loadStage((it + 1) & 1, (it + 1) * 8); cpcommit(); }

        const int st = it & 1;
        uint32_t ah[2][4], al[2][4];
        #pragma unroll
        for (int mi = 0; mi < 2; mi++) {
            int r0 = wr * 32 + mi * 16 + g;
            uint2 a0 = As[st][r0][t];
            uint2 a1 = As[st][r0 + 8][t];
            uint2 a2 = As[st][r0][4 + t];
            uint2 a3 = As[st][r0 + 8][4 + t];
            ah[mi][0] = a0.x; ah[mi][1] = a1.x; ah[mi][2] = a2.x; ah[mi][3] = a3.x;
            al[mi][0] = a0.y; al[mi][1] = a1.y; al[mi][2] = a2.y; al[mi][3] = a3.y;
        }
        #pragma unroll
        for (int ni = 0; ni < 8; ni++) {
            int c = wc * 64 + ni * 8 + g;
            uint2 b0 = Bs[st][t][c];
            uint2 b1 = Bs[st][4 + t][c];
            #pragma unroll
            for (int mi = 0; mi < 2; mi++) {
                mma_tf32(acc[mi][ni], ah[mi], b0.x, b1.x);
                mma_tf32(acc[mi][ni], al[mi], b0.x, b1.x);
                mma_tf32(acc[mi][ni], ah[mi], b0.y, b1.y);
            }
        }
        __syncthreads();
    }

    // epilogue
    #pragma unroll
    for (int mi = 0; mi < 2; mi++) {
        int r0 = by * 128 + wr * 32 + mi * 16 + g;
        #pragma unroll
        for (int ni = 0; ni < 8; ni++) {
            int c = bx * 128 + wc * 64 + ni * 8 + 2 * t;
            float v0 = acc[mi][ni][0], v1 = acc[mi][ni][1];
            float v2 = acc[mi][ni][2], v3 = acc[mi][ni][3];
            if (MODE == 0) {
                *reinterpret_cast<float2*>(g_AH + (size_t)r0 * N + c) = make_float2(v0, v1);
                *reinterpret_cast<float2*>(g_AH + (size_t)(r0 + 8) * N + c) = make_float2(v2, v3);
            }
            if (MODE == 3) {
                *reinterpret_cast<float2*>(extC + (size_t)r0 * N + c) = make_float2(v0, v1);
                *reinterpret_cast<float2*>(extC + (size_t)(r0 + 8) * N + c) = make_float2(v2, v3);
            }
            if (MODE == 1) {
                if (r0 < TOK) {   // Q float for qnorm
                    *reinterpret_cast<float2*>(g_Qf + (size_t)r0 * N + c) = make_float2(v0, v1);
                    *reinterpret_cast<float2*>(g_Qf + (size_t)(r0 + 8) * N + c) = make_float2(v2, v3);
                }
                uint2 p0 = tfsplit(v0), p1 = tfsplit(v1);
                *reinterpret_cast<uint4*>(&g_QKVs[(size_t)r0 * N + c]) = make_uint4(p0.x, p0.y, p1.x, p1.y);
                uint2 p2 = tfsplit(v2), p3 = tfsplit(v3);
                *reinterpret_cast<uint4*>(&g_QKVs[(size_t)(r0 + 8) * N + c]) = make_uint4(p2.x, p2.y, p3.x, p3.y);
            }
            if (MODE == 2) {
                uint2 p0 = tfsplit(v0), p1 = tfsplit(v1);
                *reinterpret_cast<uint4*>(&g_QKVs[(size_t)(2 * TOK + r0) * N + c]) = make_uint4(p0.x, p0.y, p1.x, p1.y);
                uint2 p2 = tfsplit(v2), p3 = tfsplit(v3);
                *reinterpret_cast<uint4*>(&g_QKVs[(size_t)(2 * TOK + r0 + 8) * N + c]) = make_uint4(p2.x, p2.y, p3.x, p3.y);
            }
        }
    }
}

// ---------------- per-token router / coefficient kernel ----------------
__global__ __launch_bounds__(128) void k_router(
    const float* __restrict__ wQg, const float* __restrict__ wKg, const float* __restrict__ wVg,
    const float* __restrict__ fqk_emb, const float* __restrict__ fv_emb,
    const float* __restrict__ Wp_qk, const float* __restrict__ bp_qk,
    const float* __restrict__ Wp_v, const float* __restrict__ bp_v,
    const float* __restrict__ Wr_qk, const float* __restrict__ Wr_v)
{
    const int t = blockIdx.x;
    const int tid = threadIdx.x;
    __shared__ float AHs[Dn];
    __shared__ float gate[3][32];
    __shared__ float hs[3][16];
    __shared__ float ins[3][128];
    __shared__ float lg[3][16];
    __shared__ float wsm[3][16];

    for (int i = tid; i < Dn; i += 128) AHs[i] = g_AH[(size_t)t * Dn + i];

    float cacc[6] = {0.f, 0.f, 0.f, 0.f, 0.f, 0.f};
    float sumAcc = 0.f;

    for (int p = 0; p < Pn; p++) {
        __syncthreads();
        if (tid < 96) {
            int router = tid >> 5, n = tid & 31;
            const float* src = (router == 0) ? wQg : ((router == 1) ? wKg : wVg);
            gate[router][n] = src[((size_t)p * TOK + t) * 32 + n];
        }
        __syncthreads();
        if (tid < 48) {
            int router = tid >> 4, r = tid & 15;
            int base = (router == 2) ? 512 : 0;
            float a = 0.f;
            #pragma unroll
            for (int n = 0; n < 32; n++) a += gate[router][n] * AHs[base + n * 16 + r];
            hs[router][r] = a;
        }
        __syncthreads();
        for (int v = tid; v < 384; v += 128) {
            int router = v >> 7, i = v & 127;
            float val;
            if (i < 64) {
                const float* Wp = (router == 2) ? Wp_v : Wp_qk;
                const float* bp = (router == 2) ? bp_v : bp_qk;
                float a = bp[i];
                #pragma unroll
                for (int r = 0; r < 16; r++) a += hs[router][r] * Wp[r * 64 + i];
                val = a;
            } else {
                int d = i - 64;
                const float* emb = (router == 2) ? fv_emb : fqk_emb;
                float a = 0.f;
                #pragma unroll
                for (int n = 0; n < 32; n++) a += gate[router][n] * emb[n * 64 + d];
                val = a;
            }
            ins[router][i] = val;
        }
        __syncthreads();
        if (tid < 48) {
            int router = tid >> 4, j = tid & 15;
            const float* Wr = (router == 2) ? Wr_v : Wr_qk;
            float a = 0.f;
            for (int i = 0; i < 128; i++) a += ins[router][i] * Wr[i * 16 + j];
            lg[router][j] = a;
        }
        __syncthreads();
        if (tid < 3) {
            float mx = -1e30f;
            for (int j = 0; j < 16; j++) mx = fmaxf(mx, lg[tid][j]);
            float e[16], s = 0.f;
            for (int j = 0; j < 16; j++) { e[j] = __expf(lg[tid][j] - mx); s += e[j]; }
            float inv = 1.f / s;
            for (int j = 0; j < 16; j++) wsm[tid][j] = e[j] * inv;
        }
        __syncthreads();
        if (tid < 48) sumAcc += wsm[tid >> 4][tid & 15];
        #pragma unroll
        for (int it = 0; it < 6; it++) {
            int v = tid + it * 128;
            int router = v >> 8, idx = v & 255;
            cacc[it] += wsm[router][idx >> 4] * hs[router][idx & 15];
        }
    }
    #pragma unroll
    for (int it = 0; it < 6; it++) {
        int v = tid + it * 128;
        int router = v >> 8, idx = v & 255;
        g_Cs[((size_t)router * TOK + t) * CDIM + idx] = tfsplit(cacc[it]);
    }
    if (tid < 48) atomicAdd(&g_rsum[tid], sumAcc);
}

// ---------------- q-norm -> scale ----------------
__global__ __launch_bounds__(256) void k_qnorm() {
    const int t = blockIdx.x;
    const int tid = threadIdx.x;
    const float* q = g_Qf + (size_t)t * Dn;
    float s = 0.f;
    for (int i = tid; i < Dn; i += 256) { float v = q[i]; s += v * v; }
    #pragma unroll
    for (int m = 16; m; m >>= 1) s += __shfl_xor_sync(0xffffffffu, s, m);
    __shared__ float red[8];
    if ((tid & 31) == 0) red[tid >> 5] = s;
    __syncthreads();
    if (tid == 0) {
        float tot = 0.f;
        for (int w = 0; w < 8; w++) tot += red[w];
        float qn = sqrtf(tot);
        g_scale[t] = (qn > 1e-6f) ? 1.0f : qn * 1e-6f;
    }
}

// ---------------- 3xtf32 flash attention, double-buffered KV ----------------
// grid (S/128, B*H), 256 threads (8 warps), warp = 16 q rows, KV tile = 32.
#define FKS 68    /* K/V row stride in pairs */
__global__ __launch_bounds__(256) void k_flashmma() {
    extern __shared__ uint2 fsm[];
    uint2* Ks = fsm;                    // [2][32][FKS]
    uint2* Vs = fsm + 2 * 32 * FKS;     // [2][32][FKS]

    const int qt = blockIdx.x;
    const int bh = blockIdx.y;
    const int b = bh >> 4, h = bh & 15;
    const int tid = threadIdx.x;
    const int lane = tid & 31;
    const int warp = tid >> 5;
    const int g = lane >> 2, t = lane & 3;
    const int q0 = qt * 128 + warp * 16;

    const uint2* Qg = g_QKVs + (size_t)b * Sn * Dn + (size_t)h * 64;
    const uint2* Kg = g_QKVs + (size_t)TOK * Dn + (size_t)b * Sn * Dn + (size_t)h * 64;
    const uint2* Vg = g_QKVs + 2 * (size_t)TOK * Dn + (size_t)b * Sn * Dn + (size_t)h * 64;

    // Q fragments (hi/lo), unscaled; 0.125 applied to S after mma
    uint32_t qh[8][4], ql[8][4];
    {
        const int r0 = q0 + g, r1 = r0 + 8;
        #pragma unroll
        for (int ka = 0; ka < 8; ka++) {
            int c = ka * 8 + t;
            uint2 s0 = Qg[(size_t)r0 * Dn + c];
            uint2 s1 = Qg[(size_t)r1 * Dn + c];
            uint2 s2 = Qg[(size_t)r0 * Dn + c + 4];
            uint2 s3 = Qg[(size_t)r1 * Dn + c + 4];
            qh[ka][0] = s0.x; qh[ka][1] = s1.x; qh[ka][2] = s2.x; qh[ka][3] = s3.x;
            ql[ka][0] = s0.y; ql[ka][1] = s1.y; ql[ka][2] = s2.y; ql[ka][3] = s3.y;
        }
    }

    float o[8][4];
    #pragma unroll
    for (int ni = 0; ni < 8; ni++)
        #pragma unroll
        for (int j = 0; j < 4; j++) o[ni][j] = 0.f;
    float m0 = -1e30f, m1 = -1e30f, l0 = 0.f, l1 = 0.f;

    const int srcA = (lane & ~3) | (t >> 1);
    const int srcB = srcA + 2;
    const bool odd = t & 1;

    const int nkt = 4 * qt + 4;

    auto loadKV = [&](int st, int kt) {
        #pragma unroll
        for (int i = 0; i < 4; i++) {
            int chunk = tid + i * 256;              // 0..1023
            int r = chunk >> 5, c4 = (chunk & 31) * 2;
            size_t go = (size_t)(kt * 32 + r) * Dn + c4;
            cpa16(&Ks[st * 32 * FKS + r * FKS + c4], Kg + go);
            cpa16(&Vs[st * 32 * FKS + r * FKS + c4], Vg + go);
        }
    };

    loadKV(0, 0);
    cpcommit();

    for (int kt = 0; kt < nkt; kt++) {
        cpwait0();
        __syncthreads();
        if (kt + 1 < nkt) { loadKV((kt + 1) & 1, kt + 1); cpcommit(); }

        if (kt * 32 > q0 + 15) continue;   // fully masked for this warp

        const uint2* Kst = Ks + (kt & 1) * 32 * FKS;
        const uint2* Vst = Vs + (kt & 1) * 32 * FKS;

        // S = Q @ K^T (16 x 32), 3xtf32
        float s[4][4];
        #pragma unroll
        for (int ni = 0; ni < 4; ni++)
            #pragma unroll
            for (int j = 0; j < 4; j++) s[ni][j] = 0.f;
        #pragma unroll
        for (int ka = 0; ka < 8; ka++) {
            #pragma unroll
            for (int ni = 0; ni < 4; ni++) {
                uint2 b0 = Kst[(ni * 8 + g) * FKS + ka * 8 + t];
                uint2 b1 = Kst[(ni * 8 + g) * FKS + ka * 8 + t + 4];
                mma_tf32(s[ni], qh[ka], b0.x, b1.x);
                mma_tf32(s[ni], ql[ka], b0.x, b1.x);
                mma_tf32(s[ni], qh[ka], b0.y, b1.y);
            }
        }
        #pragma unroll
        for (int ni = 0; ni < 4; ni++)
            #pragma unroll
            for (int j = 0; j < 4; j++) s[ni][j] *= 0.125f;

        // causal mask (diagonal tiles only)
        if (kt * 32 + 31 > q0) {
            const int r0 = q0 + g, r1 = r0 + 8, cb = kt * 32;
            #pragma unroll
            for (int ni = 0; ni < 4; ni++) {
                int c0 = cb + ni * 8 + 2 * t;
                if (c0 > r0)     s[ni][0] = -1e30f;
                if (c0 + 1 > r0) s[ni][1] = -1e30f;
                if (c0 > r1)     s[ni][2] = -1e30f;
                if (c0 + 1 > r1) s[ni][3] = -1e30f;
            }
        }

        // online softmax
        float mx0 = -1e30f, mx1 = -1e30f;
        #pragma unroll
        for (int ni = 0; ni < 4; ni++) {
            mx0 = fmaxf(mx0, fmaxf(s[ni][0], s[ni][1]));
            mx1 = fmaxf(mx1, fmaxf(s[ni][2], s[ni][3]));
        }
        mx0 = fmaxf(mx0, __shfl_xor_sync(0xffffffffu, mx0, 1));
        mx0 = fmaxf(mx0, __shfl_xor_sync(0xffffffffu, mx0, 2));
        mx1 = fmaxf(mx1, __shfl_xor_sync(0xffffffffu, mx1, 1));
        mx1 = fmaxf(mx1, __shfl_xor_sync(0xffffffffu, mx1, 2));
        float mn0 = fmaxf(m0, mx0), mn1 = fmaxf(m1, mx1);
        float cr0 = __expf(m0 - mn0), cr1 = __expf(m1 - mn1);
        m0 = mn0; m1 = mn1;
        #pragma unroll
        for (int ni = 0; ni < 8; ni++) {
            o[ni][0] *= cr0; o[ni][1] *= cr0;
            o[ni][2] *= cr1; o[ni][3] *= cr1;
        }

        // fused exp -> fragment transpose -> PV
        float rs0 = 0.f, rs1 = 0.f;
        #pragma unroll
        for (int f = 0; f < 4; f++) {
            float p0 = __expf(s[f][0] - m0);
            float p1 = __expf(s[f][1] - m0);
            float p2 = __expf(s[f][2] - m1);
            float p3 = __expf(s[f][3] - m1);
            rs0 += p0 + p1; rs1 += p2 + p3;
            uint2 t0 = tfsplit(p0), t1 = tfsplit(p1), t2 = tfsplit(p2), t3 = tfsplit(p3);
            uint32_t ph[4], pl[4];
            {
                uint32_t x0 = __shfl_sync(0xffffffffu, t0.x, srcA);
                uint32_t x1 = __shfl_sync(0xffffffffu, t1.x, srcA);
                ph[0] = odd ? x1 : x0;
                uint32_t y0 = __shfl_sync(0xffffffffu, t2.x, srcA);
                uint32_t y1 = __shfl_sync(0xffffffffu, t3.x, srcA);
                ph[1] = odd ? y1 : y0;
                uint32_t z0 = __shfl_sync(0xffffffffu, t0.x, srcB);
                uint32_t z1 = __shfl_sync(0xffffffffu, t1.x, srcB);
                ph[2] = odd ? z1 : z0;
                uint32_t w0 = __shfl_sync(0xffffffffu, t2.x, srcB);
                uint32_t w1 = __shfl_sync(0xffffffffu, t3.x, srcB);
                ph[3] = odd ? w1 : w0;
                uint32_t u0 = __shfl_sync(0xffffffffu, t0.y, srcA);
                uint32_t u1 = __shfl_sync(0xffffffffu, t1.y, srcA);
                pl[0] = odd ? u1 : u0;
                uint32_t v0 = __shfl_sync(0xffffffffu, t2.y, srcA);
                uint32_t v1 = __shfl_sync(0xffffffffu, t3.y, srcA);
                pl[1] = odd ? v1 : v0;
                uint32_t q0s = __shfl_sync(0xffffffffu, t0.y, srcB);
                uint32_t q1s = __shfl_sync(0xffffffffu, t1.y, srcB);
                pl[2] = odd ? q1s : q0s;
                uint32_t r0s = __shfl_sync(0xffffffffu, t2.y, srcB);
                uint32_t r1s = __shfl_sync(0xffffffffu, t3.y, srcB);
                pl[3] = odd ? r1s : r0s;
            }
            #pragma unroll
            for (int ni = 0; ni < 8; ni++) {
                uint2 v0 = Vst[(f * 8 + t) * FKS + ni * 8 + g];
                uint2 v1 = Vst[(f * 8 + 4 + t) * FKS + ni * 8 + g];
                mma_tf32(o[ni], ph, v0.x, v1.x);
                mma_tf32(o[ni], pl, v0.x, v1.x);
                mma_tf32(o[ni], ph, v0.y, v1.y);
            }
        }
        rs0 += __shfl_xor_sync(0xffffffffu, rs0, 1);
        rs0 += __shfl_xor_sync(0xffffffffu, rs0, 2);
        rs1 += __shfl_xor_sync(0xffffffffu, rs1, 1);
        rs1 += __shfl_xor_sync(0xffffffffu, rs1, 2);
        l0 = l0 * cr0 + rs0;
        l1 = l1 * cr1 + rs1;
    }

    // epilogue: normalize, apply q-norm scale, write split AO
    const int r0 = q0 + g, r1 = r0 + 8;
    const int tb = b * Sn;
    float f0 = g_scale[tb + r0] / l0;
    float f1 = g_scale[tb + r1] / l1;
    #pragma unroll
    for (int ni = 0; ni < 8; ni++) {
        int c = h * 64 + ni * 8 + 2 * t;
        uint2 a0 = tfsplit(o[ni][0] * f0), a1 = tfsplit(o[ni][1] * f0);
        *reinterpret_cast<uint4*>(&g_AOs[(size_t)(tb + r0) * Dn + c]) = make_uint4(a0.x, a0.y, a1.x, a1.y);
        uint2 a2 = tfsplit(o[ni][2] * f1), a3 = tfsplit(o[ni][3] * f1);
        *reinterpret_cast<uint4*>(&g_AOs[(size_t)(tb + r1) * Dn + c]) = make_uint4(a2.x, a2.y, a3.x, a3.y);
    }
}

// ---------------- aux loss ----------------
__global__ void k_aux(float* __restrict__ out) {
    float aux = 0.f;
    for (int router = 0; router < 3; router++) {
        float s = 0.f;
        for (int j = 0; j < 16; j++) {
            float mp = g_rsum[router * 16 + j] / (float)(Pn * TOK);
            s += mp * mp;
        }
        aux += 16.f * s;
    }
    out[(size_t)TOK * Dn] = aux;
}

// ---------------- launch ----------------
#define FLASH_SMEM (4 * 32 * FKS * 8)   /* 2 stages x (K+V) x 32 x FKS pairs */
extern "C" void kernel_launch(void* const* d_in, const int* in_sizes, int n_in,
                              void* d_out, int out_size) {
    const float* x       = (const float*)d_in[0];
    const float* wQ      = (const float*)d_in[1];
    const float* wK      = (const float*)d_in[2];
    const float* wV      = (const float*)d_in[3];
    const float* fneu    = (const float*)d_in[4];
    const float* rneu    = (const float*)d_in[5];
    const float* fqk_emb = (const float*)d_in[6];
    const float* fv_emb  = (const float*)d_in[7];
    const float* Wp_qk   = (const float*)d_in[8];
    const float* bp_qk   = (const float*)d_in[9];
    const float* Wp_v    = (const float*)d_in[10];
    const float* bp_v    = (const float*)d_in[11];
    const float* Wr_qk   = (const float*)d_in[12];
    const float* Wr_v    = (const float*)d_in[13];
    const float* W_O     = (const float*)d_in[14];
    float* out = (float*)d_out;

    // unconditional, idempotent (no static guards allowed in kernel_launch)
    cudaFuncSetAttribute(k_flashmma, cudaFuncAttributeMaxDynamicSharedMemorySize, FLASH_SMEM);

    k_prep<<<4096, 256>>>(fneu);
    k_split<0><<<(TOK * Dn) / 256, 256>>>(x, TOK * Dn);
    k_split<1><<<(512 * 1024) / 256, 256>>>(rneu, 512 * 1024);
    k_split<2><<<(Dn * Dn) / 256, 256>>>(W_O, Dn * Dn);
    // all_h = X @ Fall
    k_mma<0><<<dim3(Dn / 128, TOK / 128), 256>>>(nullptr);
    k_router<<<TOK, 128>>>(wQ, wK, wV, fqk_emb, fv_emb, Wp_qk, bp_qk, Wp_v, bp_v, Wr_qk, Wr_v);
    // Q,K = [CQ;CK] @ r_qk ; V = CV @ r_v
    k_mma<1><<<dim3(Dn / 128, 2 * TOK / 128), 256>>>(nullptr);
    k_mma<2><<<dim3(Dn / 128, TOK / 128), 256>>>(nullptr);
    k_qnorm<<<TOK, 256>>>();
    k_flashmma<<<dim3(Sn / 128, Bn * Hn), 256, FLASH_SMEM>>>();
    // out = AO @ W_O
    k_mma<3><<<dim3(Dn / 128, TOK / 128), 256>>>(out);
    if (out_size > TOK * Dn) k_aux<<<1, 1>>>(out);
}

// round 7
// speedup vs baseline: 2.3963x; 1.7480x over previous
#include <cuda_runtime.h>
#include <cuda_bf16.h>
#include <math.h>
#include <stdint.h>

// ---------------- problem constants ----------------
#define Pn 2
#define Bn 2
#define Sn 2048
#define Dn 1024
#define TOK 4096
#define CDIM 256

// ---------------- scratch: packed bf16x2 split planes (uint2 = {hi-pair, lo-pair}) ----------------
__device__ __align__(16) uint2 g_Xs[(size_t)TOK*512];       // x, d-pair packed
__device__ __align__(16) uint2 g_Falls[(size_t)512*1024];   // f_neurons^T, d(k)-pair packed
__device__ __align__(16) uint2 g_Rs[(size_t)256*1024];      // r_neurons (qk|v), k-pair packed
__device__ __align__(16) uint2 g_WOs[(size_t)512*1024];     // W_O, k-pair packed
__device__ __align__(16) uint2 g_Cs[(size_t)3*TOK*128];     // CQ|CK|CV, k-pair packed
__device__ __align__(16) uint2 g_Qpk[(size_t)TOK*512];      // Q, d-pair packed
__device__ __align__(16) uint2 g_Kpk[(size_t)TOK*512];      // K, d-pair packed
__device__ __align__(16) uint2 g_Vpk[(size_t)(TOK/2)*1024]; // V, key-pair packed
__device__ __align__(16) uint2 g_AOs[(size_t)TOK*512];      // attn out, d-pair packed
__device__ __align__(16) float g_AH[(size_t)TOK*Dn];        // all_h (router input)
__device__ __align__(16) float g_Qf[(size_t)TOK*Dn];        // Q float (qnorm)
__device__ __align__(16) float g_Vf[(size_t)TOK*Dn];        // V float (pack input)
__device__ float g_scale[TOK];
__device__ float g_rsum[48];

// ---------------- helpers ----------------
__device__ __forceinline__ uint32_t bf16bits(float x) {
    __nv_bfloat16 h = __float2bfloat16_rn(x);
    return (uint32_t)*reinterpret_cast<uint16_t*>(&h);
}
__device__ __forceinline__ float bf16val(uint32_t b) {
    uint16_t u = (uint16_t)b;
    __nv_bfloat16 h = *reinterpret_cast<__nv_bfloat16*>(&u);
    return __bfloat162float(h);
}
// split two floats (a = lower-k element) into packed (hi-pair, lo-pair)
__device__ __forceinline__ uint2 bfsplit2(float a, float b) {
    uint32_t ha = bf16bits(a), hb = bf16bits(b);
    uint32_t la = bf16bits(a - bf16val(ha));
    uint32_t lb = bf16bits(b - bf16val(hb));
    return make_uint2(ha | (hb << 16), la | (lb << 16));
}
__device__ __forceinline__ void mma_bf16(float* d, const uint32_t* a, uint32_t b0, uint32_t b1) {
    asm volatile("mma.sync.aligned.m16n8k16.row.col.f32.bf16.bf16.f32 "
                 "{%0,%1,%2,%3},{%4,%5,%6,%7},{%8,%9},{%0,%1,%2,%3};"
                 : "+f"(d[0]), "+f"(d[1]), "+f"(d[2]), "+f"(d[3])
                 : "r"(a[0]), "r"(a[1]), "r"(a[2]), "r"(a[3]), "r"(b0), "r"(b1));
}
__device__ __forceinline__ void cpa16(void* smem, const void* gmem) {
    uint32_t s = (uint32_t)__cvta_generic_to_shared(smem);
    asm volatile("cp.async.cg.shared.global [%0], [%1], 16;" :: "r"(s), "l"(gmem) : "memory");
}
__device__ __forceinline__ void cpcommit() { asm volatile("cp.async.commit_group;" ::: "memory"); }
__device__ __forceinline__ void cpwait0()  { asm volatile("cp.async.wait_group 0;" ::: "memory"); }

// ---------------- prep: transpose+split f_neurons, zero rsum ----------------
__global__ void k_prep(const float* __restrict__ fneu) {
    int idx = blockIdx.x * blockDim.x + threadIdx.x;
    if (blockIdx.x == 0 && threadIdx.x < 48) g_rsum[threadIdx.x] = 0.f;
    if (idx < 512 * 1024) {
        int d2 = idx >> 10, c = idx & 1023;
        int n = c >> 4, r = c & 15;
        float v0 = fneu[((size_t)n * 1024 + 2 * d2) * 16 + r];
        float v1 = fneu[((size_t)n * 1024 + 2 * d2 + 1) * 16 + r];
        g_Falls[idx] = bfsplit2(v0, v1);
    }
}

// ---------------- split kernels ----------------
template<int W>
__global__ void k_split(const float* __restrict__ src, int n) {
    int idx = blockIdx.x * blockDim.x + threadIdx.x;
    if (idx >= n) return;
    if (W == 0) {   // x: d-pair packed, contiguous
        float2 v = *reinterpret_cast<const float2*>(src + (size_t)2 * idx);
        g_Xs[idx] = bfsplit2(v.x, v.y);
    }
    if (W == 1) {   // r_neurons: k-pair packed across rows of 1024
        int k2 = idx >> 10, c = idx & 1023;
        g_Rs[idx] = bfsplit2(src[(size_t)2 * k2 * 1024 + c], src[(size_t)(2 * k2 + 1) * 1024 + c]);
    }
    if (W == 2) {   // W_O: k-pair packed across rows of 1024
        int k2 = idx >> 10, c = idx & 1023;
        g_WOs[idx] = bfsplit2(src[(size_t)2 * k2 * 1024 + c], src[(size_t)(2 * k2 + 1) * 1024 + c]);
    }
}

// pack V: key-pair packed planes
__global__ void k_packV() {
    int idx = blockIdx.x * blockDim.x + threadIdx.x;
    if (idx >= 2048 * 1024) return;
    int row2 = idx >> 10, d = idx & 1023;
    int b = row2 >> 10, kl = row2 & 1023;
    size_t tok = (size_t)b * 2048 + 2 * kl;
    g_Vpk[idx] = bfsplit2(g_Vf[tok * 1024 + d], g_Vf[(tok + 1) * 1024 + d]);
}

// ---------------- 3xbf16 double-buffered GEMM: C[M,1024] = A @ B ----------------
// block tile 128x128x16, 8 warps (4x2). Operands pre-split bf16-packed (uint2).
#define AS2 12    /* As row stride in uint2 */
#define BS2 132   /* Bs row stride in uint2 */
template<int MODE>
__global__ __launch_bounds__(256) void k_mma(float* __restrict__ extC) {
    constexpr int K2 = (MODE == 1 || MODE == 2) ? 128 : 512;   // k-pairs per row
    constexpr int N = 1024;

    const uint2* A; const uint2* B;
    if (MODE == 0) { A = g_Xs;                         B = g_Falls; }
    if (MODE == 1) { A = g_Cs;                         B = g_Rs; }
    if (MODE == 2) { A = g_Cs + (size_t)2 * TOK * 128; B = g_Rs + (size_t)128 * 1024; }
    if (MODE == 3) { A = g_AOs;                        B = g_WOs; }

    __shared__ uint2 As[2][128][AS2];
    __shared__ uint2 Bs[2][8][BS2];

    const int tid  = threadIdx.x;
    const int lane = tid & 31;
    const int warp = tid >> 5;
    const int wr = warp >> 1;
    const int wc = warp & 1;
    const int g = lane >> 2;
    const int t = lane & 3;
    const int bx = blockIdx.x, by = blockIdx.y;

    float acc[2][8][4];
    #pragma unroll
    for (int mi = 0; mi < 2; mi++)
        #pragma unroll
        for (int ni = 0; ni < 8; ni++)
            #pragma unroll
            for (int j = 0; j < 4; j++) acc[mi][ni][j] = 0.f;

    const uint2* Ab = A + (size_t)by * 128 * K2;
    const uint2* Bb = B + (size_t)bx * 128;

    auto loadStage = [&](int st, int k20) {
        #pragma unroll
        for (int i = 0; i < 2; i++) {
            int chunk = tid + i * 256;              // A: 512 chunks of 16B
            int r = chunk >> 2, cc = (chunk & 3) * 2;
            cpa16(&As[st][r][cc], Ab + (size_t)r * K2 + k20 + cc);
        }
        #pragma unroll
        for (int i = 0; i < 2; i++) {
            int chunk = tid + i * 256;              // B: 512 chunks of 16B
            int kr = chunk >> 6, cc = (chunk & 63) * 2;
            cpa16(&Bs[st][kr][cc], Bb + (size_t)(k20 + kr) * N + cc);
        }
    };

    loadStage(0, 0);
    cpcommit();

    constexpr int NIT = K2 / 8;   // BK = 16 elements = 8 pairs
    for (int it = 0; it < NIT; it++) {
        cpwait0();
        __syncthreads();
        if (it + 1 < NIT) { loadStage((it + 1) & 1, (it + 1) * 8); cpcommit(); }

        const int st = it & 1;
        uint32_t ah[2][4], al[2][4];
        #pragma unroll
        for (int mi = 0; mi < 2; mi++) {
            int r0 = wr * 32 + mi * 16 + g;
            uint2 a0 = As[st][r0][t];
            uint2 a1 = As[st][r0 + 8][t];
            uint2 a2 = As[st][r0][t + 4];
            uint2 a3 = As[st][r0 + 8][t + 4];
            ah[mi][0] = a0.x; ah[mi][1] = a1.x; ah[mi][2] = a2.x; ah[mi][3] = a3.x;
            al[mi][0] = a0.y; al[mi][1] = a1.y; al[mi][2] = a2.y; al[mi][3] = a3.y;
        }
        #pragma unroll
        for (int ni = 0; ni < 8; ni++) {
            int c = wc * 64 + ni * 8 + g;
            uint2 b0 = Bs[st][t][c];
            uint2 b1 = Bs[st][t + 4][c];
            #pragma unroll
            for (int mi = 0; mi < 2; mi++) {
                mma_bf16(acc[mi][ni], ah[mi], b0.x, b1.x);
                mma_bf16(acc[mi][ni], al[mi], b0.x, b1.x);
                mma_bf16(acc[mi][ni], ah[mi], b0.y, b1.y);
            }
        }
        __syncthreads();
    }

    // epilogue
    #pragma unroll
    for (int mi = 0; mi < 2; mi++) {
        int r0 = by * 128 + wr * 32 + mi * 16 + g;
        #pragma unroll
        for (int ni = 0; ni < 8; ni++) {
            int c = bx * 128 + wc * 64 + ni * 8 + 2 * t;
            int cp = c >> 1;    // packed column
            float v0 = acc[mi][ni][0], v1 = acc[mi][ni][1];
            float v2 = acc[mi][ni][2], v3 = acc[mi][ni][3];
            if (MODE == 0) {
                *reinterpret_cast<float2*>(g_AH + (size_t)r0 * N + c) = make_float2(v0, v1);
                *reinterpret_cast<float2*>(g_AH + (size_t)(r0 + 8) * N + c) = make_float2(v2, v3);
            }
            if (MODE == 3) {
                *reinterpret_cast<float2*>(extC + (size_t)r0 * N + c) = make_float2(v0, v1);
                *reinterpret_cast<float2*>(extC + (size_t)(r0 + 8) * N + c) = make_float2(v2, v3);
            }
            if (MODE == 1) {
                if (r0 < TOK) {   // Q rows
                    *reinterpret_cast<float2*>(g_Qf + (size_t)r0 * N + c) = make_float2(v0, v1);
                    *reinterpret_cast<float2*>(g_Qf + (size_t)(r0 + 8) * N + c) = make_float2(v2, v3);
                    g_Qpk[(size_t)r0 * 512 + cp] = bfsplit2(v0, v1);
                    g_Qpk[(size_t)(r0 + 8) * 512 + cp] = bfsplit2(v2, v3);
                } else {          // K rows
                    g_Kpk[(size_t)(r0 - TOK) * 512 + cp] = bfsplit2(v0, v1);
                    g_Kpk[(size_t)(r0 + 8 - TOK) * 512 + cp] = bfsplit2(v2, v3);
                }
            }
            if (MODE == 2) {      // V float (packed later by k_packV)
                *reinterpret_cast<float2*>(g_Vf + (size_t)r0 * N + c) = make_float2(v0, v1);
                *reinterpret_cast<float2*>(g_Vf + (size_t)(r0 + 8) * N + c) = make_float2(v2, v3);
            }
        }
    }
}

// ---------------- per-token router / coefficient kernel ----------------
__global__ __launch_bounds__(128) void k_router(
    const float* __restrict__ wQg, const float* __restrict__ wKg, const float* __restrict__ wVg,
    const float* __restrict__ fqk_emb, const float* __restrict__ fv_emb,
    const float* __restrict__ Wp_qk, const float* __restrict__ bp_qk,
    const float* __restrict__ Wp_v, const float* __restrict__ bp_v,
    const float* __restrict__ Wr_qk, const float* __restrict__ Wr_v)
{
    const int t = blockIdx.x;
    const int tid = threadIdx.x;
    __shared__ float AHs[Dn];
    __shared__ float gate[3][32];
    __shared__ float hs[3][16];
    __shared__ float ins[3][128];
    __shared__ float lg[3][16];
    __shared__ float wsm[3][16];
    __shared__ float cbuf[768];

    for (int i = tid; i < Dn; i += 128) AHs[i] = g_AH[(size_t)t * Dn + i];

    float cacc[6] = {0.f, 0.f, 0.f, 0.f, 0.f, 0.f};
    float sumAcc = 0.f;

    for (int p = 0; p < Pn; p++) {
        __syncthreads();
        if (tid < 96) {
            int router = tid >> 5, n = tid & 31;
            const float* src = (router == 0) ? wQg : ((router == 1) ? wKg : wVg);
            gate[router][n] = src[((size_t)p * TOK + t) * 32 + n];
        }
        __syncthreads();
        if (tid < 48) {
            int router = tid >> 4, r = tid & 15;
            int base = (router == 2) ? 512 : 0;
            float a = 0.f;
            #pragma unroll
            for (int n = 0; n < 32; n++) a += gate[router][n] * AHs[base + n * 16 + r];
            hs[router][r] = a;
        }
        __syncthreads();
        for (int v = tid; v < 384; v += 128) {
            int router = v >> 7, i = v & 127;
            float val;
            if (i < 64) {
                const float* Wp = (router == 2) ? Wp_v : Wp_qk;
                const float* bp = (router == 2) ? bp_v : bp_qk;
                float a = bp[i];
                #pragma unroll
                for (int r = 0; r < 16; r++) a += hs[router][r] * Wp[r * 64 + i];
                val = a;
            } else {
                int d = i - 64;
                const float* emb = (router == 2) ? fv_emb : fqk_emb;
                float a = 0.f;
                #pragma unroll
                for (int n = 0; n < 32; n++) a += gate[router][n] * emb[n * 64 + d];
                val = a;
            }
            ins[router][i] = val;
        }
        __syncthreads();
        if (tid < 48) {
            int router = tid >> 4, j = tid & 15;
            const float* Wr = (router == 2) ? Wr_v : Wr_qk;
            float a = 0.f;
            for (int i = 0; i < 128; i++) a += ins[router][i] * Wr[i * 16 + j];
            lg[router][j] = a;
        }
        __syncthreads();
        if (tid < 3) {
            float mx = -1e30f;
            for (int j = 0; j < 16; j++) mx = fmaxf(mx, lg[tid][j]);
            float e[16], s = 0.f;
            for (int j = 0; j < 16; j++) { e[j] = __expf(lg[tid][j] - mx); s += e[j]; }
            float inv = 1.f / s;
            for (int j = 0; j < 16; j++) wsm[tid][j] = e[j] * inv;
        }
        __syncthreads();
        if (tid < 48) sumAcc += wsm[tid >> 4][tid & 15];
        #pragma unroll
        for (int it = 0; it < 6; it++) {
            int v = tid + it * 128;
            int router = v >> 8, idx = v & 255;
            cacc[it] += wsm[router][idx >> 4] * hs[router][idx & 15];
        }
    }
    #pragma unroll
    for (int it = 0; it < 6; it++) cbuf[tid + it * 128] = cacc[it];
    __syncthreads();
    for (int j = tid; j < 384; j += 128) {
        int router = j >> 7, j2 = j & 127;
        g_Cs[((size_t)router * TOK + t) * 128 + j2] =
            bfsplit2(cbuf[router * 256 + 2 * j2], cbuf[router * 256 + 2 * j2 + 1]);
    }
    if (tid < 48) atomicAdd(&g_rsum[tid], sumAcc);
}

// ---------------- q-norm -> scale ----------------
__global__ __launch_bounds__(256) void k_qnorm() {
    const int t = blockIdx.x;
    const int tid = threadIdx.x;
    const float* q = g_Qf + (size_t)t * Dn;
    float s = 0.f;
    for (int i = tid; i < Dn; i += 256) { float v = q[i]; s += v * v; }
    #pragma unroll
    for (int m = 16; m; m >>= 1) s += __shfl_xor_sync(0xffffffffu, s, m);
    __shared__ float red[8];
    if ((tid & 31) == 0) red[tid >> 5] = s;
    __syncthreads();
    if (tid == 0) {
        float tot = 0.f;
        for (int w = 0; w < 8; w++) tot += red[w];
        float qn = sqrtf(tot);
        g_scale[t] = (qn > 1e-6f) ? 1.0f : qn * 1e-6f;
    }
}

// ---------------- 3xbf16 flash attention, double-buffered KV ----------------
// grid (S/128, B*H), 256 threads (8 warps), warp = 16 q rows, KV tile = 32.
#define KS2 36   /* K row stride in uint2 */
#define VS2 68   /* V row stride in uint2 */
__global__ __launch_bounds__(256) void k_flashmma() {
    __shared__ uint2 Ks[2][32][KS2];
    __shared__ uint2 Vs[2][16][VS2];

    const int qt = blockIdx.x;
    const int bh = blockIdx.y;
    const int b = bh >> 4, h = bh & 15;
    const int tid = threadIdx.x;
    const int lane = tid & 31;
    const int warp = tid >> 5;
    const int g = lane >> 2, t = lane & 3;
    const int q0 = qt * 128 + warp * 16;

    // Q fragments (hi/lo), 4 k16 chunks over DH=64
    uint32_t qh[4][4], ql[4][4];
    {
        const uint2* Qr0 = g_Qpk + (size_t)(b * Sn + q0 + g) * 512 + h * 32;
        const uint2* Qr1 = g_Qpk + (size_t)(b * Sn + q0 + g + 8) * 512 + h * 32;
        #pragma unroll
        for (int kc = 0; kc < 4; kc++) {
            uint2 a0 = Qr0[kc * 8 + t];
            uint2 a1 = Qr1[kc * 8 + t];
            uint2 a2 = Qr0[kc * 8 + t + 4];
            uint2 a3 = Qr1[kc * 8 + t + 4];
            qh[kc][0] = a0.x; qh[kc][1] = a1.x; qh[kc][2] = a2.x; qh[kc][3] = a3.x;
            ql[kc][0] = a0.y; ql[kc][1] = a1.y; ql[kc][2] = a2.y; ql[kc][3] = a3.y;
        }
    }

    float o[8][4];
    #pragma unroll
    for (int ni = 0; ni < 8; ni++)
        #pragma unroll
        for (int j = 0; j < 4; j++) o[ni][j] = 0.f;
    float m0 = -1e30f, m1 = -1e30f, l0 = 0.f, l1 = 0.f;

    const int nkt = 4 * qt + 4;

    auto loadKV = [&](int st, int kt) {
        #pragma unroll
        for (int i = 0; i < 4; i++) {
            int chunk = tid + i * 256;              // 0..1023
            if (chunk < 512) {
                int r = chunk >> 4, cc = (chunk & 15) * 2;
                cpa16(&Ks[st][r][cc],
                      g_Kpk + (size_t)(b * Sn + kt * 32 + r) * 512 + h * 32 + cc);
            } else {
                int c2 = chunk - 512;
                int r = c2 >> 5, cc = (c2 & 31) * 2;
                cpa16(&Vs[st][r][cc],
                      g_Vpk + (size_t)(b * (Sn / 2) + kt * 16 + r) * 1024 + h * 64 + cc);
            }
        }
    };

    loadKV(0, 0);
    cpcommit();

    for (int kt = 0; kt < nkt; kt++) {
        cpwait0();
        __syncthreads();
        if (kt + 1 < nkt) { loadKV((kt + 1) & 1, kt + 1); cpcommit(); }

        if (kt * 32 > q0 + 15) continue;   // fully masked for this warp
        const int st = kt & 1;

        // S = Q @ K^T (16 x 32), 3xbf16
        float s[4][4];
        #pragma unroll
        for (int ni = 0; ni < 4; ni++)
            #pragma unroll
            for (int j = 0; j < 4; j++) s[ni][j] = 0.f;
        #pragma unroll
        for (int kc = 0; kc < 4; kc++) {
            #pragma unroll
            for (int ni = 0; ni < 4; ni++) {
                uint2 b0 = Ks[st][ni * 8 + g][kc * 8 + t];
                uint2 b1 = Ks[st][ni * 8 + g][kc * 8 + t + 4];
                mma_bf16(s[ni], qh[kc], b0.x, b1.x);
                mma_bf16(s[ni], ql[kc], b0.x, b1.x);
                mma_bf16(s[ni], qh[kc], b0.y, b1.y);
            }
        }
        #pragma unroll
        for (int ni = 0; ni < 4; ni++)
            #pragma unroll
            for (int j = 0; j < 4; j++) s[ni][j] *= 0.125f;

        // causal mask (diagonal tiles only)
        if (kt * 32 + 31 > q0) {
            const int r0 = q0 + g, r1 = r0 + 8, cb = kt * 32;
            #pragma unroll
            for (int ni = 0; ni < 4; ni++) {
                int c0 = cb + ni * 8 + 2 * t;
                if (c0 > r0)     s[ni][0] = -1e30f;
                if (c0 + 1 > r0) s[ni][1] = -1e30f;
                if (c0 > r1)     s[ni][2] = -1e30f;
                if (c0 + 1 > r1) s[ni][3] = -1e30f;
            }
        }

        // online softmax
        float mx0 = -1e30f, mx1 = -1e30f;
        #pragma unroll
        for (int ni = 0; ni < 4; ni++) {
            mx0 = fmaxf(mx0, fmaxf(s[ni][0], s[ni][1]));
            mx1 = fmaxf(mx1, fmaxf(s[ni][2], s[ni][3]));
        }
        mx0 = fmaxf(mx0, __shfl_xor_sync(0xffffffffu, mx0, 1));
        mx0 = fmaxf(mx0, __shfl_xor_sync(0xffffffffu, mx0, 2));
        mx1 = fmaxf(mx1, __shfl_xor_sync(0xffffffffu, mx1, 1));
        mx1 = fmaxf(mx1, __shfl_xor_sync(0xffffffffu, mx1, 2));
        float mn0 = fmaxf(m0, mx0), mn1 = fmaxf(m1, mx1);
        float cr0 = __expf(m0 - mn0), cr1 = __expf(m1 - mn1);
        m0 = mn0; m1 = mn1;
        #pragma unroll
        for (int ni = 0; ni < 8; ni++) {
            o[ni][0] *= cr0; o[ni][1] *= cr0;
            o[ni][2] *= cr1; o[ni][3] *= cr1;
        }

        // exp in place; row sums
        float rs0 = 0.f, rs1 = 0.f;
        #pragma unroll
        for (int ni = 0; ni < 4; ni++) {
            s[ni][0] = __expf(s[ni][0] - m0);
            s[ni][1] = __expf(s[ni][1] - m0);
            s[ni][2] = __expf(s[ni][2] - m1);
            s[ni][3] = __expf(s[ni][3] - m1);
            rs0 += s[ni][0] + s[ni][1];
            rs1 += s[ni][2] + s[ni][3];
        }
        rs0 += __shfl_xor_sync(0xffffffffu, rs0, 1);
        rs0 += __shfl_xor_sync(0xffffffffu, rs0, 2);
        rs1 += __shfl_xor_sync(0xffffffffu, rs1, 1);
        rs1 += __shfl_xor_sync(0xffffffffu, rs1, 2);
        l0 = l0 * cr0 + rs0;
        l1 = l1 * cr1 + rs1;

        // P@V: C-fragment == A-fragment layout for bf16 — no shuffles
        #pragma unroll
        for (int kc = 0; kc < 2; kc++) {
            uint32_t pH[4], pL[4];
            uint2 f0 = bfsplit2(s[2 * kc][0], s[2 * kc][1]);
            uint2 f1 = bfsplit2(s[2 * kc][2], s[2 * kc][3]);
            uint2 f2 = bfsplit2(s[2 * kc + 1][0], s[2 * kc + 1][1]);
            uint2 f3 = bfsplit2(s[2 * kc + 1][2], s[2 * kc + 1][3]);
            pH[0] = f0.x; pH[1] = f1.x; pH[2] = f2.x; pH[3] = f3.x;
            pL[0] = f0.y; pL[1] = f1.y; pL[2] = f2.y; pL[3] = f3.y;
            #pragma unroll
            for (int ni = 0; ni < 8; ni++) {
                uint2 b0 = Vs[st][kc * 8 + t][ni * 8 + g];
                uint2 b1 = Vs[st][kc * 8 + t + 4][ni * 8 + g];
                mma_bf16(o[ni], pH, b0.x, b1.x);
                mma_bf16(o[ni], pL, b0.x, b1.x);
                mma_bf16(o[ni], pH, b0.y, b1.y);
            }
        }
    }

    // epilogue: normalize, q-norm scale, write packed AO
    const int r0 = q0 + g, r1 = r0 + 8;
    const int tb = b * Sn;
    float f0 = g_scale[tb + r0] / l0;
    float f1 = g_scale[tb + r1] / l1;
    #pragma unroll
    for (int ni = 0; ni < 8; ni++) {
        int cp = h * 32 + ni * 4 + t;
        g_AOs[(size_t)(tb + r0) * 512 + cp] = bfsplit2(o[ni][0] * f0, o[ni][1] * f0);
        g_AOs[(size_t)(tb + r1) * 512 + cp] = bfsplit2(o[ni][2] * f1, o[ni][3] * f1);
    }
}

// ---------------- aux loss ----------------
__global__ void k_aux(float* __restrict__ out) {
    float aux = 0.f;
    for (int router = 0; router < 3; router++) {
        float s = 0.f;
        for (int j = 0; j < 16; j++) {
            float mp = g_rsum[router * 16 + j] / (float)(Pn * TOK);
            s += mp * mp;
        }
        aux += 16.f * s;
    }
    out[(size_t)TOK * Dn] = aux;
}

// ---------------- launch ----------------
extern "C" void kernel_launch(void* const* d_in, const int* in_sizes, int n_in,
                              void* d_out, int out_size) {
    const float* x       = (const float*)d_in[0];
    const float* wQ      = (const float*)d_in[1];
    const float* wK      = (const float*)d_in[2];
    const float* wV      = (const float*)d_in[3];
    const float* fneu    = (const float*)d_in[4];
    const float* rneu    = (const float*)d_in[5];
    const float* fqk_emb = (const float*)d_in[6];
    const float* fv_emb  = (const float*)d_in[7];
    const float* Wp_qk   = (const float*)d_in[8];
    const float* bp_qk   = (const float*)d_in[9];
    const float* Wp_v    = (const float*)d_in[10];
    const float* bp_v    = (const float*)d_in[11];
    const float* Wr_qk   = (const float*)d_in[12];
    const float* Wr_v    = (const float*)d_in[13];
    const float* W_O     = (const float*)d_in[14];
    float* out = (float*)d_out;

    k_prep<<<2048, 256>>>(fneu);
    k_split<0><<<(TOK * 512) / 256, 256>>>(x, TOK * 512);
    k_split<1><<<(256 * 1024) / 256, 256>>>(rneu, 256 * 1024);
    k_split<2><<<(512 * 1024) / 256, 256>>>(W_O, 512 * 1024);
    // all_h = X @ Fall
    k_mma<0><<<dim3(8, 32), 256>>>(nullptr);
    k_router<<<TOK, 128>>>(wQ, wK, wV, fqk_emb, fv_emb, Wp_qk, bp_qk, Wp_v, bp_v, Wr_qk, Wr_v);
    // Q,K = [CQ;CK] @ r_qk ; V = CV @ r_v
    k_mma<1><<<dim3(8, 64), 256>>>(nullptr);
    k_mma<2><<<dim3(8, 32), 256>>>(nullptr);
    k_packV<<<(2048 * 1024) / 256, 256>>>();
    k_qnorm<<<TOK, 256>>>();
    k_flashmma<<<dim3(Sn / 128, Bn * 16), 256>>>();
    // out = AO @ W_O
    k_mma<3><<<dim3(8, 32), 256>>>(out);
    if (out_size > TOK * Dn) k_aux<<<1, 1>>>(out);
}

// round 8
// speedup vs baseline: 2.4488x; 1.0219x over previous
#include <cuda_runtime.h>
#include <cuda_bf16.h>
#include <math.h>
#include <stdint.h>

// ---------------- problem constants ----------------
#define Pn 2
#define Bn 2
#define Sn 2048
#define Dn 1024
#define TOK 4096

// ---------------- scratch: packed bf16x2 split planes (uint2 = {hi-pair, lo-pair}) ----------------
__device__ __align__(16) uint2 g_Xs[(size_t)TOK*512];       // x, d-pair packed
__device__ __align__(16) uint2 g_Falls[(size_t)512*1024];   // f_neurons^T, d(k)-pair packed
__device__ __align__(16) uint2 g_Rs[(size_t)256*1024];      // r_neurons (qk|v), k-pair packed
__device__ __align__(16) uint2 g_WOs[(size_t)512*1024];     // W_O, k-pair packed
__device__ __align__(16) uint2 g_Cs[(size_t)3*TOK*128];     // CQ|CK|CV, k-pair packed
__device__ __align__(16) uint2 g_Qpk[(size_t)TOK*512];      // Q, d-pair packed
__device__ __align__(16) uint2 g_Kpk[(size_t)TOK*512];      // K, d-pair packed
__device__ __align__(16) uint2 g_Vpk[(size_t)(TOK/2)*1024]; // V, key-pair packed
__device__ __align__(16) uint2 g_AOs[(size_t)TOK*512];      // attn out, d-pair packed
__device__ __align__(16) float g_AH[(size_t)TOK*Dn];        // all_h (router input)
__device__ __align__(16) float g_Vf[(size_t)TOK*Dn];        // V float (pack input)
__device__ float g_qsq[TOK];                                // |Q|^2 partials
__device__ float g_rsum[48];

// ---------------- helpers ----------------
__device__ __forceinline__ uint32_t bf16bits(float x) {
    __nv_bfloat16 h = __float2bfloat16_rn(x);
    return (uint32_t)*reinterpret_cast<uint16_t*>(&h);
}
__device__ __forceinline__ float bf16val(uint32_t b) {
    uint16_t u = (uint16_t)b;
    __nv_bfloat16 h = *reinterpret_cast<__nv_bfloat16*>(&u);
    return __bfloat162float(h);
}
__device__ __forceinline__ uint2 bfsplit2(float a, float b) {
    uint32_t ha = bf16bits(a), hb = bf16bits(b);
    uint32_t la = bf16bits(a - bf16val(ha));
    uint32_t lb = bf16bits(b - bf16val(hb));
    return make_uint2(ha | (hb << 16), la | (lb << 16));
}
__device__ __forceinline__ void mma_bf16(float* d, const uint32_t* a, uint32_t b0, uint32_t b1) {
    asm volatile("mma.sync.aligned.m16n8k16.row.col.f32.bf16.bf16.f32 "
                 "{%0,%1,%2,%3},{%4,%5,%6,%7},{%8,%9},{%0,%1,%2,%3};"
                 : "+f"(d[0]), "+f"(d[1]), "+f"(d[2]), "+f"(d[3])
                 : "r"(a[0]), "r"(a[1]), "r"(a[2]), "r"(a[3]), "r"(b0), "r"(b1));
}
__device__ __forceinline__ void cpa16(void* smem, const void* gmem) {
    uint32_t s = (uint32_t)__cvta_generic_to_shared(smem);
    asm volatile("cp.async.cg.shared.global [%0], [%1], 16;" :: "r"(s), "l"(gmem) : "memory");
}
__device__ __forceinline__ void cpcommit() { asm volatile("cp.async.commit_group;" ::: "memory"); }
template<int N>
__device__ __forceinline__ void cpwaitN() { asm volatile("cp.async.wait_group %0;" :: "n"(N) : "memory"); }

// ---------------- prep: transpose+split f_neurons, zero accumulators ----------------
__global__ void k_prep(const float* __restrict__ fneu) {
    int idx = blockIdx.x * blockDim.x + threadIdx.x;
    if (blockIdx.x == 0 && threadIdx.x < 48) g_rsum[threadIdx.x] = 0.f;
    if (idx < TOK) g_qsq[idx] = 0.f;
    if (idx < 512 * 1024) {
        int d2 = idx >> 10, c = idx & 1023;
        int n = c >> 4, r = c & 15;
        float v0 = fneu[((size_t)n * 1024 + 2 * d2) * 16 + r];
        float v1 = fneu[((size_t)n * 1024 + 2 * d2 + 1) * 16 + r];
        g_Falls[idx] = bfsplit2(v0, v1);
    }
}

// ---------------- split kernels ----------------
template<int W>
__global__ void k_split(const float* __restrict__ src, int n) {
    int idx = blockIdx.x * blockDim.x + threadIdx.x;
    if (idx >= n) return;
    if (W == 0) {
        float2 v = *reinterpret_cast<const float2*>(src + (size_t)2 * idx);
        g_Xs[idx] = bfsplit2(v.x, v.y);
    }
    if (W == 1) {
        int k2 = idx >> 10, c = idx & 1023;
        g_Rs[idx] = bfsplit2(src[(size_t)2 * k2 * 1024 + c], src[(size_t)(2 * k2 + 1) * 1024 + c]);
    }
    if (W == 2) {
        int k2 = idx >> 10, c = idx & 1023;
        g_WOs[idx] = bfsplit2(src[(size_t)2 * k2 * 1024 + c], src[(size_t)(2 * k2 + 1) * 1024 + c]);
    }
}

// pack V: key-pair packed planes
__global__ void k_packV() {
    int idx = blockIdx.x * blockDim.x + threadIdx.x;
    if (idx >= 2048 * 1024) return;
    int row2 = idx >> 10, d = idx & 1023;
    int b = row2 >> 10, kl = row2 & 1023;
    size_t tok = (size_t)b * 2048 + 2 * kl;
    g_Vpk[idx] = bfsplit2(g_Vf[tok * 1024 + d], g_Vf[(tok + 1) * 1024 + d]);
}

// ---------------- 3xbf16 GEMM, 3-stage cp.async pipeline ----------------
// block tile 128x128x16, 8 warps (4x2). Operands pre-split bf16-packed (uint2).
#define AS2 12    /* As row stride in uint2 */
#define BS2 132   /* Bs row stride in uint2 */
#define GEMM_SMEM ((3*128*AS2 + 3*8*BS2) * 8)
template<int MODE>
__global__ __launch_bounds__(256) void k_mma(float* __restrict__ extC) {
    constexpr int K2 = (MODE == 1 || MODE == 2) ? 128 : 512;   // k-pairs per row
    constexpr int N = 1024;
    constexpr int NIT = K2 / 8;

    const uint2* A; const uint2* B;
    if (MODE == 0) { A = g_Xs;                         B = g_Falls; }
    if (MODE == 1) { A = g_Cs;                         B = g_Rs; }
    if (MODE == 2) { A = g_Cs + (size_t)2 * TOK * 128; B = g_Rs + (size_t)128 * 1024; }
    if (MODE == 3) { A = g_AOs;                        B = g_WOs; }

    extern __shared__ uint2 sm[];
    uint2* As = sm;                    // [3][128][AS2]
    uint2* Bs = sm + 3 * 128 * AS2;    // [3][8][BS2]

    const int tid  = threadIdx.x;
    const int lane = tid & 31;
    const int warp = tid >> 5;
    const int wr = warp >> 1;
    const int wc = warp & 1;
    const int g = lane >> 2;
    const int t = lane & 3;
    const int bx = blockIdx.x, by = blockIdx.y;

    float acc[2][8][4];
    #pragma unroll
    for (int mi = 0; mi < 2; mi++)
        #pragma unroll
        for (int ni = 0; ni < 8; ni++)
            #pragma unroll
            for (int j = 0; j < 4; j++) acc[mi][ni][j] = 0.f;

    const uint2* Ab = A + (size_t)by * 128 * K2;
    const uint2* Bb = B + (size_t)bx * 128;

    auto loadStage = [&](int st, int k20) {
        #pragma unroll
        for (int i = 0; i < 2; i++) {
            int chunk = tid + i * 256;
            int r = chunk >> 2, cc = (chunk & 3) * 2;
            cpa16(&As[(st * 128 + r) * AS2 + cc], Ab + (size_t)r * K2 + k20 + cc);
        }
        #pragma unroll
        for (int i = 0; i < 2; i++) {
            int chunk = tid + i * 256;
            int kr = chunk >> 6, cc = (chunk & 63) * 2;
            cpa16(&Bs[(st * 8 + kr) * BS2 + cc], Bb + (size_t)(k20 + kr) * N + cc);
        }
    };

    loadStage(0, 0); cpcommit();
    loadStage(1, 8); cpcommit();

    for (int it = 0; it < NIT; it++) {
        if (it + 1 < NIT) cpwaitN<1>(); else cpwaitN<0>();
        __syncthreads();
        if (it + 2 < NIT) { loadStage((it + 2) % 3, (it + 2) * 8); cpcommit(); }

        const int st = it % 3;
        uint32_t ah[2][4], al[2][4];
        #pragma unroll
        for (int mi = 0; mi < 2; mi++) {
            int r0 = wr * 32 + mi * 16 + g;
            uint2 a0 = As[(st * 128 + r0) * AS2 + t];
            uint2 a1 = As[(st * 128 + r0 + 8) * AS2 + t];
            uint2 a2 = As[(st * 128 + r0) * AS2 + t + 4];
            uint2 a3 = As[(st * 128 + r0 + 8) * AS2 + t + 4];
            ah[mi][0] = a0.x; ah[mi][1] = a1.x; ah[mi][2] = a2.x; ah[mi][3] = a3.x;
            al[mi][0] = a0.y; al[mi][1] = a1.y; al[mi][2] = a2.y; al[mi][3] = a3.y;
        }
        #pragma unroll
        for (int ni = 0; ni < 8; ni++) {
            int c = wc * 64 + ni * 8 + g;
            uint2 b0 = Bs[(st * 8 + t) * BS2 + c];
            uint2 b1 = Bs[(st * 8 + t + 4) * BS2 + c];
            #pragma unroll
            for (int mi = 0; mi < 2; mi++) {
                mma_bf16(acc[mi][ni], ah[mi], b0.x, b1.x);
                mma_bf16(acc[mi][ni], al[mi], b0.x, b1.x);
                mma_bf16(acc[mi][ni], ah[mi], b0.y, b1.y);
            }
        }
    }

    // epilogue
    #pragma unroll
    for (int mi = 0; mi < 2; mi++) {
        int r0 = by * 128 + wr * 32 + mi * 16 + g;
        float qs0 = 0.f, qs1 = 0.f;
        #pragma unroll
        for (int ni = 0; ni < 8; ni++) {
            int c = bx * 128 + wc * 64 + ni * 8 + 2 * t;
            int cp = c >> 1;
            float v0 = acc[mi][ni][0], v1 = acc[mi][ni][1];
            float v2 = acc[mi][ni][2], v3 = acc[mi][ni][3];
            if (MODE == 0) {
                *reinterpret_cast<float2*>(g_AH + (size_t)r0 * N + c) = make_float2(v0, v1);
                *reinterpret_cast<float2*>(g_AH + (size_t)(r0 + 8) * N + c) = make_float2(v2, v3);
            }
            if (MODE == 3) {
                *reinterpret_cast<float2*>(extC + (size_t)r0 * N + c) = make_float2(v0, v1);
                *reinterpret_cast<float2*>(extC + (size_t)(r0 + 8) * N + c) = make_float2(v2, v3);
            }
            if (MODE == 1) {
                if (r0 < TOK) {   // Q rows
                    qs0 += v0 * v0 + v1 * v1;
                    qs1 += v2 * v2 + v3 * v3;
                    g_Qpk[(size_t)r0 * 512 + cp] = bfsplit2(v0, v1);
                    g_Qpk[(size_t)(r0 + 8) * 512 + cp] = bfsplit2(v2, v3);
                } else {          // K rows
                    g_Kpk[(size_t)(r0 - TOK) * 512 + cp] = bfsplit2(v0, v1);
                    g_Kpk[(size_t)(r0 + 8 - TOK) * 512 + cp] = bfsplit2(v2, v3);
                }
            }
            if (MODE == 2) {      // V float (packed later by k_packV)
                *reinterpret_cast<float2*>(g_Vf + (size_t)r0 * N + c) = make_float2(v0, v1);
                *reinterpret_cast<float2*>(g_Vf + (size_t)(r0 + 8) * N + c) = make_float2(v2, v3);
            }
        }
        if (MODE == 1 && r0 < TOK) {
            atomicAdd(&g_qsq[r0], qs0);
            atomicAdd(&g_qsq[r0 + 8], qs1);
        }
    }
}

// ---------------- per-token router / coefficient kernel ----------------
__global__ __launch_bounds__(128) void k_router(
    const float* __restrict__ wQg, const float* __restrict__ wKg, const float* __restrict__ wVg,
    const float* __restrict__ fqk_emb, const float* __restrict__ fv_emb,
    const float* __restrict__ Wp_qk, const float* __restrict__ bp_qk,
    const float* __restrict__ Wp_v, const float* __restrict__ bp_v,
    const float* __restrict__ Wr_qk, const float* __restrict__ Wr_v)
{
    const int t = blockIdx.x;
    const int tid = threadIdx.x;
    __shared__ float AHs[Dn];
    __shared__ float gate[3][32];
    __shared__ float hs[3][16];
    __shared__ float ins[3][128];
    __shared__ float lg[3][16];
    __shared__ float wsm[3][16];
    __shared__ float cbuf[768];

    for (int i = tid; i < Dn; i += 128) AHs[i] = g_AH[(size_t)t * Dn + i];

    float cacc[6] = {0.f, 0.f, 0.f, 0.f, 0.f, 0.f};
    float sumAcc = 0.f;

    for (int p = 0; p < Pn; p++) {
        __syncthreads();
        if (tid < 96) {
            int router = tid >> 5, n = tid & 31;
            const float* src = (router == 0) ? wQg : ((router == 1) ? wKg : wVg);
            gate[router][n] = src[((size_t)p * TOK + t) * 32 + n];
        }
        __syncthreads();
        if (tid < 48) {
            int router = tid >> 4, r = tid & 15;
            int base = (router == 2) ? 512 : 0;
            float a = 0.f;
            #pragma unroll
            for (int n = 0; n < 32; n++) a += gate[router][n] * AHs[base + n * 16 + r];
            hs[router][r] = a;
        }
        __syncthreads();
        for (int v = tid; v < 384; v += 128) {
            int router = v >> 7, i = v & 127;
            float val;
            if (i < 64) {
                const float* Wp = (router == 2) ? Wp_v : Wp_qk;
                const float* bp = (router == 2) ? bp_v : bp_qk;
                float a = bp[i];
                #pragma unroll
                for (int r = 0; r < 16; r++) a += hs[router][r] * Wp[r * 64 + i];
                val = a;
            } else {
                int d = i - 64;
                const float* emb = (router == 2) ? fv_emb : fqk_emb;
                float a = 0.f;
                #pragma unroll
                for (int n = 0; n < 32; n++) a += gate[router][n] * emb[n * 64 + d];
                val = a;
            }
            ins[router][i] = val;
        }
        __syncthreads();
        if (tid < 48) {
            int router = tid >> 4, j = tid & 15;
            const float* Wr = (router == 2) ? Wr_v : Wr_qk;
            float a = 0.f;
            for (int i = 0; i < 128; i++) a += ins[router][i] * Wr[i * 16 + j];
            lg[router][j] = a;
        }
        __syncthreads();
        if (tid < 3) {
            float mx = -1e30f;
            for (int j = 0; j < 16; j++) mx = fmaxf(mx, lg[tid][j]);
            float e[16], s = 0.f;
            for (int j = 0; j < 16; j++) { e[j] = __expf(lg[tid][j] - mx); s += e[j]; }
            float inv = 1.f / s;
            for (int j = 0; j < 16; j++) wsm[tid][j] = e[j] * inv;
        }
        __syncthreads();
        if (tid < 48) sumAcc += wsm[tid >> 4][tid & 15];
        #pragma unroll
        for (int it = 0; it < 6; it++) {
            int v = tid + it * 128;
            int router = v >> 8, idx = v & 255;
            cacc[it] += wsm[router][idx >> 4] * hs[router][idx & 15];
        }
    }
    #pragma unroll
    for (int it = 0; it < 6; it++) cbuf[tid + it * 128] = cacc[it];
    __syncthreads();
    for (int j = tid; j < 384; j += 128) {
        int router = j >> 7, j2 = j & 127;
        g_Cs[((size_t)router * TOK + t) * 128 + j2] =
            bfsplit2(cbuf[router * 256 + 2 * j2], cbuf[router * 256 + 2 * j2 + 1]);
    }
    if (tid < 48) atomicAdd(&g_rsum[tid], sumAcc);
}

// ---------------- 3xbf16 flash attention, 3-stage cp.async pipeline ----------------
// grid (S/128, B*H), 256 threads (8 warps), warp = 16 q rows, KV tile = 32.
#define KS2 36   /* K row stride in uint2 */
#define VS2 68   /* V row stride in uint2 */
#define FLASH_SMEM ((3*32*KS2 + 3*16*VS2) * 8)
__global__ __launch_bounds__(256) void k_flashmma() {
    extern __shared__ uint2 fsm[];
    uint2* Ks = fsm;                   // [3][32][KS2]
    uint2* Vs = fsm + 3 * 32 * KS2;    // [3][16][VS2]

    const int qt = blockIdx.x;
    const int bh = blockIdx.y;
    const int b = bh >> 4, h = bh & 15;
    const int tid = threadIdx.x;
    const int lane = tid & 31;
    const int warp = tid >> 5;
    const int g = lane >> 2, t = lane & 3;
    const int q0 = qt * 128 + warp * 16;

    // Q fragments (hi/lo), 4 k16 chunks over DH=64
    uint32_t qh[4][4], ql[4][4];
    {
        const uint2* Qr0 = g_Qpk + (size_t)(b * Sn + q0 + g) * 512 + h * 32;
        const uint2* Qr1 = g_Qpk + (size_t)(b * Sn + q0 + g + 8) * 512 + h * 32;
        #pragma unroll
        for (int kc = 0; kc < 4; kc++) {
            uint2 a0 = Qr0[kc * 8 + t];
            uint2 a1 = Qr1[kc * 8 + t];
            uint2 a2 = Qr0[kc * 8 + t + 4];
            uint2 a3 = Qr1[kc * 8 + t + 4];
            qh[kc][0] = a0.x; qh[kc][1] = a1.x; qh[kc][2] = a2.x; qh[kc][3] = a3.x;
            ql[kc][0] = a0.y; ql[kc][1] = a1.y; ql[kc][2] = a2.y; ql[kc][3] = a3.y;
        }
    }

    float o[8][4];
    #pragma unroll
    for (int ni = 0; ni < 8; ni++)
        #pragma unroll
        for (int j = 0; j < 4; j++) o[ni][j] = 0.f;
    float m0 = -1e30f, m1 = -1e30f, l0 = 0.f, l1 = 0.f;

    const int nkt = 4 * qt + 4;

    auto loadKV = [&](int st, int kt) {
        #pragma unroll
        for (int i = 0; i < 4; i++) {
            int chunk = tid + i * 256;
            if (chunk < 512) {
                int r = chunk >> 4, cc = (chunk & 15) * 2;
                cpa16(&Ks[(st * 32 + r) * KS2 + cc],
                      g_Kpk + (size_t)(b * Sn + kt * 32 + r) * 512 + h * 32 + cc);
            } else {
                int c2 = chunk - 512;
                int r = c2 >> 5, cc = (c2 & 31) * 2;
                cpa16(&Vs[(st * 16 + r) * VS2 + cc],
                      g_Vpk + (size_t)(b * (Sn / 2) + kt * 16 + r) * 1024 + h * 64 + cc);
            }
        }
    };

    loadKV(0, 0); cpcommit();
    loadKV(1, 1); cpcommit();

    for (int kt = 0; kt < nkt; kt++) {
        if (kt + 1 < nkt) cpwaitN<1>(); else cpwaitN<0>();
        __syncthreads();
        if (kt + 2 < nkt) { loadKV((kt + 2) % 3, kt + 2); cpcommit(); }

        if (kt * 32 > q0 + 15) continue;   // fully masked for this warp
        const int st = kt % 3;

        // S = Q @ K^T (16 x 32), 3xbf16
        float s[4][4];
        #pragma unroll
        for (int ni = 0; ni < 4; ni++)
            #pragma unroll
            for (int j = 0; j < 4; j++) s[ni][j] = 0.f;
        #pragma unroll
        for (int kc = 0; kc < 4; kc++) {
            #pragma unroll
            for (int ni = 0; ni < 4; ni++) {
                uint2 b0 = Ks[(st * 32 + ni * 8 + g) * KS2 + kc * 8 + t];
                uint2 b1 = Ks[(st * 32 + ni * 8 + g) * KS2 + kc * 8 + t + 4];
                mma_bf16(s[ni], qh[kc], b0.x, b1.x);
                mma_bf16(s[ni], ql[kc], b0.x, b1.x);
                mma_bf16(s[ni], qh[kc], b0.y, b1.y);
            }
        }
        #pragma unroll
        for (int ni = 0; ni < 4; ni++)
            #pragma unroll
            for (int j = 0; j < 4; j++) s[ni][j] *= 0.125f;

        // causal mask (diagonal tiles only)
        if (kt * 32 + 31 > q0) {
            const int r0 = q0 + g, r1 = r0 + 8, cb = kt * 32;
            #pragma unroll
            for (int ni = 0; ni < 4; ni++) {
                int c0 = cb + ni * 8 + 2 * t;
                if (c0 > r0)     s[ni][0] = -1e30f;
                if (c0 + 1 > r0) s[ni][1] = -1e30f;
                if (c0 > r1)     s[ni][2] = -1e30f;
                if (c0 + 1 > r1) s[ni][3] = -1e30f;
            }
        }

        // online softmax
        float mx0 = -1e30f, mx1 = -1e30f;
        #pragma unroll
        for (int ni = 0; ni < 4; ni++) {
            mx0 = fmaxf(mx0, fmaxf(s[ni][0], s[ni][1]));
            mx1 = fmaxf(mx1, fmaxf(s[ni][2], s[ni][3]));
        }
        mx0 = fmaxf(mx0, __shfl_xor_sync(0xffffffffu, mx0, 1));
        mx0 = fmaxf(mx0, __shfl_xor_sync(0xffffffffu, mx0, 2));
        mx1 = fmaxf(mx1, __shfl_xor_sync(0xffffffffu, mx1, 1));
        mx1 = fmaxf(mx1, __shfl_xor_sync(0xffffffffu, mx1, 2));
        float mn0 = fmaxf(m0, mx0), mn1 = fmaxf(m1, mx1);
        float cr0 = __expf(m0 - mn0), cr1 = __expf(m1 - mn1);
        m0 = mn0; m1 = mn1;
        #pragma unroll
        for (int ni = 0; ni < 8; ni++) {
            o[ni][0] *= cr0; o[ni][1] *= cr0;
            o[ni][2] *= cr1; o[ni][3] *= cr1;
        }

        // exp in place; row sums
        float rs0 = 0.f, rs1 = 0.f;
        #pragma unroll
        for (int ni = 0; ni < 4; ni++) {
            s[ni][0] = __expf(s[ni][0] - m0);
            s[ni][1] = __expf(s[ni][1] - m0);
            s[ni][2] = __expf(s[ni][2] - m1);
            s[ni][3] = __expf(s[ni][3] - m1);
            rs0 += s[ni][0] + s[ni][1];
            rs1 += s[ni][2] + s[ni][3];
        }
        rs0 += __shfl_xor_sync(0xffffffffu, rs0, 1);
        rs0 += __shfl_xor_sync(0xffffffffu, rs0, 2);
        rs1 += __shfl_xor_sync(0xffffffffu, rs1, 1);
        rs1 += __shfl_xor_sync(0xffffffffu, rs1, 2);
        l0 = l0 * cr0 + rs0;
        l1 = l1 * cr1 + rs1;

        // P@V: C-fragment == A-fragment layout for bf16 — no shuffles
        #pragma unroll
        for (int kc = 0; kc < 2; kc++) {
            uint32_t pH[4], pL[4];
            uint2 f0 = bfsplit2(s[2 * kc][0], s[2 * kc][1]);
            uint2 f1 = bfsplit2(s[2 * kc][2], s[2 * kc][3]);
            uint2 f2 = bfsplit2(s[2 * kc + 1][0], s[2 * kc + 1][1]);
            uint2 f3 = bfsplit2(s[2 * kc + 1][2], s[2 * kc + 1][3]);
            pH[0] = f0.x; pH[1] = f1.x; pH[2] = f2.x; pH[3] = f3.x;
            pL[0] = f0.y; pL[1] = f1.y; pL[2] = f2.y; pL[3] = f3.y;
            #pragma unroll
            for (int ni = 0; ni < 8; ni++) {
                uint2 b0 = Vs[(st * 16 + kc * 8 + t) * VS2 + ni * 8 + g];
                uint2 b1 = Vs[(st * 16 + kc * 8 + t + 4) * VS2 + ni * 8 + g];
                mma_bf16(o[ni], pH, b0.x, b1.x);
                mma_bf16(o[ni], pL, b0.x, b1.x);
                mma_bf16(o[ni], pH, b0.y, b1.y);
            }
        }
    }

    // epilogue: normalize, q-norm scale (from g_qsq), write packed AO
    const int r0 = q0 + g, r1 = r0 + 8;
    const int tb = b * Sn;
    float qsq0 = g_qsq[tb + r0], qsq1 = g_qsq[tb + r1];
    float sc0 = (qsq0 > 1e-12f) ? 1.f : sqrtf(qsq0) * 1e-6f;
    float sc1 = (qsq1 > 1e-12f) ? 1.f : sqrtf(qsq1) * 1e-6f;
    float f0 = sc0 / l0;
    float f1 = sc1 / l1;
    #pragma unroll
    for (int ni = 0; ni < 8; ni++) {
        int cp = h * 32 + ni * 4 + t;
        g_AOs[(size_t)(tb + r0) * 512 + cp] = bfsplit2(o[ni][0] * f0, o[ni][1] * f0);
        g_AOs[(size_t)(tb + r1) * 512 + cp] = bfsplit2(o[ni][2] * f1, o[ni][3] * f1);
    }
}

// ---------------- aux loss ----------------
__global__ void k_aux(float* __restrict__ out) {
    float aux = 0.f;
    for (int router = 0; router < 3; router++) {
        float s = 0.f;
        for (int j = 0; j < 16; j++) {
            float mp = g_rsum[router * 16 + j] / (float)(Pn * TOK);
            s += mp * mp;
        }
        aux += 16.f * s;
    }
    out[(size_t)TOK * Dn] = aux;
}

// ---------------- launch ----------------
extern "C" void kernel_launch(void* const* d_in, const int* in_sizes, int n_in,
                              void* d_out, int out_size) {
    const float* x       = (const float*)d_in[0];
    const float* wQ      = (const float*)d_in[1];
    const float* wK      = (const float*)d_in[2];
    const float* wV      = (const float*)d_in[3];
    const float* fneu    = (const float*)d_in[4];
    const float* rneu    = (const float*)d_in[5];
    const float* fqk_emb = (const float*)d_in[6];
    const float* fv_emb  = (const float*)d_in[7];
    const float* Wp_qk   = (const float*)d_in[8];
    const float* bp_qk   = (const float*)d_in[9];
    const float* Wp_v    = (const float*)d_in[10];
    const float* bp_v    = (const float*)d_in[11];
    const float* Wr_qk   = (const float*)d_in[12];
    const float* Wr_v    = (const float*)d_in[13];
    const float* W_O     = (const float*)d_in[14];
    float* out = (float*)d_out;

    // unconditional, idempotent
    cudaFuncSetAttribute(k_mma<0>, cudaFuncAttributeMaxDynamicSharedMemorySize, GEMM_SMEM);
    cudaFuncSetAttribute(k_mma<1>, cudaFuncAttributeMaxDynamicSharedMemorySize, GEMM_SMEM);
    cudaFuncSetAttribute(k_mma<2>, cudaFuncAttributeMaxDynamicSharedMemorySize, GEMM_SMEM);
    cudaFuncSetAttribute(k_mma<3>, cudaFuncAttributeMaxDynamicSharedMemorySize, GEMM_SMEM);
    cudaFuncSetAttribute(k_flashmma, cudaFuncAttributeMaxDynamicSharedMemorySize, FLASH_SMEM);

    k_prep<<<2048, 256>>>(fneu);
    k_split<0><<<(TOK * 512) / 256, 256>>>(x, TOK * 512);
    k_split<1><<<(256 * 1024) / 256, 256>>>(rneu, 256 * 1024);
    k_split<2><<<(512 * 1024) / 256, 256>>>(W_O, 512 * 1024);
    // all_h = X @ Fall
    k_mma<0><<<dim3(8, 32), 256, GEMM_SMEM>>>(nullptr);
    k_router<<<TOK, 128>>>(wQ, wK, wV, fqk_emb, fv_emb, Wp_qk, bp_qk, Wp_v, bp_v, Wr_qk, Wr_v);
    // Q,K = [CQ;CK] @ r_qk ; V = CV @ r_v
    k_mma<1><<<dim3(8, 64), 256, GEMM_SMEM>>>(nullptr);
    k_mma<2><<<dim3(8, 32), 256, GEMM_SMEM>>>(nullptr);
    k_packV<<<(2048 * 1024) / 256, 256>>>();
    k_flashmma<<<dim3(Sn / 128, Bn * 16), 256, FLASH_SMEM>>>();
    // out = AO @ W_O
    k_mma<3><<<dim3(8, 32), 256, GEMM_SMEM>>>(out);
    if (out_size > TOK * Dn) k_aux<<<1, 1>>>(out);
}